// round 9
// baseline (speedup 1.0000x reference)
#include <cuda_runtime.h>
#include <math.h>
#include <stdint.h>

#define Bc 4
#define Sc 2048
#define Ec 1024
#define Hc 16
#define Dc 64
#define Mtot (Bc*Sc)   // 8192

// Scratch (static device globals: allocation-free)
__device__ float g_Q[(size_t)Bc*Hc*Sc*Dc];
__device__ float g_K[(size_t)Bc*Hc*Sc*Dc];
__device__ float g_V[(size_t)Bc*Hc*Sc*Dc];
__device__ float g_A[(size_t)Bc*Sc*Ec];

// ---- helpers --------------------------------------------------------------
__device__ __forceinline__ uint32_t f2tf(float x) {
    uint32_t u;
    asm("cvt.rna.tf32.f32 %0, %1;" : "=r"(u) : "f"(x));
    return u;
}

__device__ __forceinline__ void mma8(float* d, const uint32_t* a, const uint32_t* b) {
    asm volatile(
        "mma.sync.aligned.m16n8k8.row.col.f32.tf32.tf32.f32 "
        "{%0,%1,%2,%3}, {%4,%5,%6,%7}, {%8,%9}, {%0,%1,%2,%3};"
        : "+f"(d[0]), "+f"(d[1]), "+f"(d[2]), "+f"(d[3])
        : "r"(a[0]), "r"(a[1]), "r"(a[2]), "r"(a[3]), "r"(b[0]), "r"(b[1]));
}

__device__ __forceinline__ void cpa16(uint32_t dst, const void* src) {
    asm volatile("cp.async.cg.shared.global [%0], [%1], 16;" :: "r"(dst), "l"(src));
}
__device__ __forceinline__ void cp_commit() {
    asm volatile("cp.async.commit_group;" ::: "memory");
}
__device__ __forceinline__ void cp_wait0() {
    asm volatile("cp.async.wait_group 0;" ::: "memory");
}

// Convert 4 consecutive f32 words in smem to tf32 bits, in place.
__device__ __forceinline__ void cvt4(float* p) {
    float4 v = *(float4*)p;
    uint4 u = make_uint4(f2tf(v.x), f2tf(v.y), f2tf(v.z), f2tf(v.w));
    *(uint4*)p = u;
}

// ---------------- GEMM: C[M,1024] = A[M,1024] @ W[1024,1024] + bias --------
// 128x128 tile, BK=32, 256 threads (8 warps), warp tile 64x32.
// cp.async double buffer; producer-side in-place f32->tf32 convert.
// As stride 36 (bank 4g+tg CF), Ws stride 136 (bank 8tg+g CF).
#define GBM 128
#define GBN 128
#define GBK 32
#define ASTR 36
#define WSTR 136
#define ASTG (GBM*ASTR)       // 4608 words / stage
#define WSTG (GBK*WSTR)       // 4352 words / stage
#define GSM  (2*(ASTG+WSTG))  // 17920 words = 71680 B

__global__ __launch_bounds__(256, 2) void gemm_tc(
    const float* __restrict__ A, const float* __restrict__ W,
    const float* __restrict__ bias, float* __restrict__ C, int split)
{
    extern __shared__ float smf[];
    float* Asb = smf;                 // 2 stages [128][36]
    float* Wsb = smf + 2 * ASTG;      // 2 stages [32][136]

    const int tid  = threadIdx.x;
    const int lane = tid & 31, warp = tid >> 5;
    const int g = lane >> 2, tg = lane & 3;
    const int wm = warp >> 2, wn = warp & 3;
    const int bm = blockIdx.y * GBM, bn = blockIdx.x * GBN;

    // copy mappings
    const int ar = tid >> 1;                 // A row 0..127
    const int ac = (tid & 1) * 16;           // A col word base (+4j)
    const int wr = tid >> 3;                 // W row 0..31
    const int wc = (tid & 7) * 16;           // W col word base (+4j)
    const float* Ab = A + (size_t)(bm + ar) * Ec + ac;
    const float* Wb = W + (size_t)wr * Ec + bn + wc;

    const uint32_t asA = (uint32_t)__cvta_generic_to_shared(Asb) + (ar * ASTR + ac) * 4;
    const uint32_t asW = (uint32_t)__cvta_generic_to_shared(Wsb) + (wr * WSTR + wc) * 4;

    float acc[4][4][4];
    #pragma unroll
    for (int mt = 0; mt < 4; mt++)
        #pragma unroll
        for (int nt = 0; nt < 4; nt++)
            #pragma unroll
            for (int i = 0; i < 4; i++) acc[mt][nt][i] = 0.f;

    // prologue: stage 0
    #pragma unroll
    for (int j = 0; j < 4; j++) cpa16(asA + 16 * j, Ab + 4 * j);
    #pragma unroll
    for (int j = 0; j < 4; j++) cpa16(asW + 16 * j, Wb + 4 * j);
    cp_commit();

    const int NIT = Ec / GBK;   // 32
    for (int it = 0; it < NIT; it++) {
        const int p = it & 1;
        cp_wait0();
        __syncthreads();           // stage p data visible to all

        // producer-side convert stage p (in place)
        {
            float* Ax = Asb + p * ASTG + ar * ASTR;       // this thread's A row
            cvt4(Ax + ac + 0); cvt4(Ax + ac + 4);
            cvt4(Ax + ac + 8); cvt4(Ax + ac + 12);
            float* Wx = Wsb + p * WSTG + wr * WSTR + wc;
            cvt4(Wx + 0); cvt4(Wx + 4); cvt4(Wx + 8); cvt4(Wx + 12);
        }
        __syncthreads();           // converted tile visible; stage 1-p fully drained

        if (it + 1 < NIT) {
            const int k0 = (it + 1) * GBK;
            const uint32_t dA = asA + (1 - p) * ASTG * 4;
            const uint32_t dW = asW + (1 - p) * WSTG * 4;
            #pragma unroll
            for (int j = 0; j < 4; j++) cpa16(dA + 16 * j, Ab + k0 + 4 * j);
            #pragma unroll
            for (int j = 0; j < 4; j++) cpa16(dW + 16 * j, Wb + (size_t)k0 * Ec + 4 * j);
            cp_commit();
        }

        const uint32_t* As = (const uint32_t*)(Asb + p * ASTG);
        const uint32_t* Ws = (const uint32_t*)(Wsb + p * WSTG);

        #pragma unroll
        for (int ks = 0; ks < 4; ks++) {
            uint32_t af[4][4], bf[4][2];
            #pragma unroll
            for (int mt = 0; mt < 4; mt++) {
                const int r = wm * 64 + mt * 16 + g;
                af[mt][0] = As[r * ASTR + ks * 8 + tg];
                af[mt][1] = As[(r + 8) * ASTR + ks * 8 + tg];
                af[mt][2] = As[r * ASTR + ks * 8 + tg + 4];
                af[mt][3] = As[(r + 8) * ASTR + ks * 8 + tg + 4];
            }
            #pragma unroll
            for (int nt = 0; nt < 4; nt++) {
                const int cb = wn * 32 + nt * 8 + g;
                bf[nt][0] = Ws[(ks * 8 + tg) * WSTR + cb];
                bf[nt][1] = Ws[(ks * 8 + tg + 4) * WSTR + cb];
            }
            #pragma unroll
            for (int mt = 0; mt < 4; mt++)
                #pragma unroll
                for (int nt = 0; nt < 4; nt++)
                    mma8(acc[mt][nt], af[mt], bf[nt]);
        }
    }

    #pragma unroll
    for (int mt = 0; mt < 4; mt++) {
        #pragma unroll
        for (int half = 0; half < 2; half++) {
            const int m = bm + wm * 64 + mt * 16 + g + half * 8;
            #pragma unroll
            for (int nt = 0; nt < 4; nt++) {
                const int n = bn + wn * 32 + nt * 8 + 2 * tg;
                float2 bb = *(const float2*)&bias[n];
                float v0 = acc[mt][nt][half * 2 + 0] + bb.x;
                float v1 = acc[mt][nt][half * 2 + 1] + bb.y;
                if (split) {
                    const int b = m >> 11, s = m & 2047;
                    const int h = n >> 6, d = n & 63;
                    *(float2*)&C[(((size_t)(b * Hc + h)) * Sc + s) * Dc + d] =
                        make_float2(v0, v1);
                } else {
                    *(float2*)&C[(size_t)m * Ec + n] = make_float2(v0, v1);
                }
            }
        }
    }
}

// ---------------- Flash attention (tf32 mma, P in regs, cp.async) ----------
// 128 q / CTA, 8 warps. Smem tiles converted to tf32 in place by producer.
// S-MMA B rows permuted by pi(n)=(n>>1)+4(n&1) so the S accumulator is
// directly the PV A-fragment (P never stored).
#define AQ 128
#define QST 68
#define KST 68
#define VST 72
#define KSTG (64*KST)   // 4352
#define VSTG (64*VST)   // 4608
#define ASM_W (128*QST + 2*KSTG + 2*VSTG)   // 26624 words = 106496 B

__global__ __launch_bounds__(256, 2) void attn_tc(
    const float* __restrict__ Qg_, const float* __restrict__ Kg_,
    const float* __restrict__ Vg_, float* __restrict__ Ag_)
{
    extern __shared__ float smf[];
    float* Qs = smf;                       // [128][68]
    float* Kb = smf + 128 * QST;           // 2 x [64][68]
    float* Vb = Kb + 2 * KSTG;             // 2 x [64][72]

    const int tid  = threadIdx.x;
    const int lane = tid & 31, warp = tid >> 5;
    const int g = lane >> 2, tg = lane & 3;
    const int q0 = warp * 16;
    const int pig = (g >> 1) + 4 * (g & 1);

    const int qt = blockIdx.x, h = blockIdx.y, b = blockIdx.z;
    const size_t headOff = ((size_t)(b * Hc + h)) * Sc * Dc;
    const float* Qg = Qg_ + headOff + (size_t)qt * AQ * Dc;
    const float* Kg = Kg_ + headOff;
    const float* Vg = Vg_ + headOff;

    // copy mappings
    const int qr = tid >> 1, qc = (tid & 1) * 32;          // Q: 8 chunks
    const int kr = tid >> 2, kc = (tid & 3) * 16;          // K/V: 4 chunks
    const uint32_t sQ = (uint32_t)__cvta_generic_to_shared(Qs) + (qr * QST + qc) * 4;
    const uint32_t sK = (uint32_t)__cvta_generic_to_shared(Kb) + (kr * KST + kc) * 4;
    const uint32_t sV = (uint32_t)__cvta_generic_to_shared(Vb) + (kr * VST + kc) * 4;
    const float* Kgr = Kg + (size_t)kr * Dc + kc;
    const float* Vgr = Vg + (size_t)kr * Dc + kc;

    // prologue: Q + tile 0 (one group)
    #pragma unroll
    for (int j = 0; j < 8; j++) cpa16(sQ + 16 * j, Qg + (size_t)qr * Dc + qc + 4 * j);
    #pragma unroll
    for (int j = 0; j < 4; j++) cpa16(sK + 16 * j, Kgr + 4 * j);
    #pragma unroll
    for (int j = 0; j < 4; j++) cpa16(sV + 16 * j, Vgr + 4 * j);
    cp_commit();

    float o[8][4];
    float mrow[2], lrow[2];
    #pragma unroll
    for (int nt = 0; nt < 8; nt++)
        #pragma unroll
        for (int i = 0; i < 4; i++) o[nt][i] = 0.f;
    mrow[0] = mrow[1] = -INFINITY;
    lrow[0] = lrow[1] = 0.f;

    const int NT = Sc / 64;   // 32
    for (int kt = 0; kt < NT; kt++) {
        const int p = kt & 1;
        cp_wait0();
        __syncthreads();       // tile p (and Q on kt==0) visible

        // producer-side convert (in place)
        if (kt == 0) {
            float* Qx = Qs + qr * QST + qc;
            #pragma unroll
            for (int j = 0; j < 8; j++) cvt4(Qx + 4 * j);
        }
        {
            float* Kx = Kb + p * KSTG + kr * KST + kc;
            cvt4(Kx + 0); cvt4(Kx + 4); cvt4(Kx + 8); cvt4(Kx + 12);
            float* Vx = Vb + p * VSTG + kr * VST + kc;
            cvt4(Vx + 0); cvt4(Vx + 4); cvt4(Vx + 8); cvt4(Vx + 12);
        }
        __syncthreads();       // converted; stage 1-p fully drained by all warps

        if (kt + 1 < NT) {
            const size_t off = (size_t)(kt + 1) * 64 * Dc;
            const uint32_t dK = sK + (1 - p) * KSTG * 4;
            const uint32_t dV = sV + (1 - p) * VSTG * 4;
            #pragma unroll
            for (int j = 0; j < 4; j++) cpa16(dK + 16 * j, Kgr + off + 4 * j);
            #pragma unroll
            for (int j = 0; j < 4; j++) cpa16(dV + 16 * j, Vgr + off + 4 * j);
            cp_commit();
        }

        const uint32_t* Qu = (const uint32_t*)Qs;
        const uint32_t* Ks = (const uint32_t*)(Kb + p * KSTG);
        const uint32_t* Vs = (const uint32_t*)(Vb + p * VSTG);

        // S = Q K^T (B rows taken at 8nt + pig)
        float s[8][4];
        #pragma unroll
        for (int nt = 0; nt < 8; nt++)
            #pragma unroll
            for (int i = 0; i < 4; i++) s[nt][i] = 0.f;

        #pragma unroll
        for (int ks = 0; ks < 8; ks++) {
            uint32_t af[4];
            af[0] = Qu[(q0 + g) * QST + ks * 8 + tg];
            af[1] = Qu[(q0 + 8 + g) * QST + ks * 8 + tg];
            af[2] = Qu[(q0 + g) * QST + ks * 8 + tg + 4];
            af[3] = Qu[(q0 + 8 + g) * QST + ks * 8 + tg + 4];
            #pragma unroll
            for (int nt = 0; nt < 8; nt++) {
                const uint32_t* kp = Ks + (nt * 8 + pig) * KST;
                uint32_t bf[2];
                bf[0] = kp[ks * 8 + tg];
                bf[1] = kp[ks * 8 + tg + 4];
                mma8(s[nt], af, bf);
            }
        }
        // thread holds S(q0+g+8h, kv=8nt+tg) in s[nt][2h], kv=8nt+tg+4 in s[nt][2h+1]

        // Online softmax (scale 0.125 applied here; rows spread over 4-lane quad)
        #pragma unroll
        for (int half = 0; half < 2; half++) {
            float tmax = -INFINITY;
            #pragma unroll
            for (int nt = 0; nt < 8; nt++) {
                s[nt][half * 2 + 0] *= 0.125f;
                s[nt][half * 2 + 1] *= 0.125f;
                tmax = fmaxf(tmax, s[nt][half * 2 + 0]);
                tmax = fmaxf(tmax, s[nt][half * 2 + 1]);
            }
            tmax = fmaxf(tmax, __shfl_xor_sync(0xffffffffu, tmax, 1));
            tmax = fmaxf(tmax, __shfl_xor_sync(0xffffffffu, tmax, 2));
            const float mn   = fmaxf(mrow[half], tmax);
            const float corr = __expf(mrow[half] - mn);
            float rs = 0.f;
            #pragma unroll
            for (int nt = 0; nt < 8; nt++) {
                float p0 = __expf(s[nt][half * 2 + 0] - mn);
                float p1 = __expf(s[nt][half * 2 + 1] - mn);
                s[nt][half * 2 + 0] = p0;
                s[nt][half * 2 + 1] = p1;
                rs += p0 + p1;
                o[nt][half * 2 + 0] *= corr;
                o[nt][half * 2 + 1] *= corr;
            }
            rs += __shfl_xor_sync(0xffffffffu, rs, 1);
            rs += __shfl_xor_sync(0xffffffffu, rs, 2);
            lrow[half] = lrow[half] * corr + rs;
            mrow[half] = mn;
        }

        // O += P @ V : P fragments straight from S accumulator
        #pragma unroll
        for (int ks = 0; ks < 8; ks++) {
            uint32_t af[4];
            af[0] = f2tf(s[ks][0]);
            af[1] = f2tf(s[ks][2]);
            af[2] = f2tf(s[ks][1]);
            af[3] = f2tf(s[ks][3]);
            const uint32_t* v0 = Vs + (ks * 8 + tg) * VST;
            const uint32_t* v1 = Vs + (ks * 8 + tg + 4) * VST;
            #pragma unroll
            for (int nt = 0; nt < 8; nt++) {
                uint32_t bf[2];
                bf[0] = v0[nt * 8 + g];
                bf[1] = v1[nt * 8 + g];
                mma8(o[nt], af, bf);
            }
        }
    }

    // Epilogue: normalize, write concat layout [B,S,E]
    #pragma unroll
    for (int half = 0; half < 2; half++) {
        const float inv = 1.f / lrow[half];
        const int q = qt * AQ + q0 + g + half * 8;
        #pragma unroll
        for (int nt = 0; nt < 8; nt++) {
            const int d = nt * 8 + 2 * tg;
            *(float2*)&Ag_[((size_t)b * Sc + q) * Ec + h * Dc + d] =
                make_float2(o[nt][half * 2 + 0] * inv, o[nt][half * 2 + 1] * inv);
        }
    }
}

// ---------------------------------------------------------------------------
extern "C" void kernel_launch(void* const* d_in, const int* in_sizes, int n_in,
                              void* d_out, int out_size)
{
    const float* x  = (const float*)d_in[0];
    const float* Wq = (const float*)d_in[1];
    const float* bq = (const float*)d_in[2];
    const float* Wk = (const float*)d_in[3];
    const float* bk = (const float*)d_in[4];
    const float* Wv = (const float*)d_in[5];
    const float* bv = (const float*)d_in[6];
    const float* Wo = (const float*)d_in[7];
    const float* bo = (const float*)d_in[8];
    float* out = (float*)d_out;

    float *pQ, *pK, *pV, *pA;
    cudaGetSymbolAddress((void**)&pQ, g_Q);
    cudaGetSymbolAddress((void**)&pK, g_K);
    cudaGetSymbolAddress((void**)&pV, g_V);
    cudaGetSymbolAddress((void**)&pA, g_A);

    const int gemmSmem = GSM * 4;      // 71680 B
    const int attnSmem = ASM_W * 4;    // 106496 B
    cudaFuncSetAttribute(gemm_tc, cudaFuncAttributeMaxDynamicSharedMemorySize, gemmSmem);
    cudaFuncSetAttribute(attn_tc, cudaFuncAttributeMaxDynamicSharedMemorySize, attnSmem);

    dim3 gg(Ec / GBN, Mtot / GBM);   // (8, 64)
    gemm_tc<<<gg, 256, gemmSmem>>>(x, Wq, bq, pQ, 1);
    gemm_tc<<<gg, 256, gemmSmem>>>(x, Wk, bk, pK, 1);
    gemm_tc<<<gg, 256, gemmSmem>>>(x, Wv, bv, pV, 1);
    attn_tc<<<dim3(Sc / AQ, Hc, Bc), 256, attnSmem>>>(pQ, pK, pV, pA);
    gemm_tc<<<gg, 256, gemmSmem>>>(pA, Wo, bo, out, 0);
}

// round 10
// speedup vs baseline: 1.3074x; 1.3074x over previous
#include <cuda_runtime.h>
#include <math.h>
#include <stdint.h>

#define Bc 4
#define Sc 2048
#define Ec 1024
#define Hc 16
#define Dc 64
#define Mtot (Bc*Sc)   // 8192

// Scratch (static device globals: allocation-free)
// g_Q/g_K/g_V/g_A hold tf32 BIT PATTERNS stored as float.
__device__ float g_Q[(size_t)Bc*Hc*Sc*Dc];
__device__ float g_K[(size_t)Bc*Hc*Sc*Dc];
__device__ float g_V[(size_t)Bc*Hc*Sc*Dc];
__device__ float g_A[(size_t)Bc*Sc*Ec];

// ---- helpers --------------------------------------------------------------
__device__ __forceinline__ uint32_t f2tf(float x) {
    uint32_t u;
    asm("cvt.rna.tf32.f32 %0, %1;" : "=r"(u) : "f"(x));
    return u;
}

__device__ __forceinline__ void mma8(float* d, const uint32_t* a, const uint32_t* b) {
    asm volatile(
        "mma.sync.aligned.m16n8k8.row.col.f32.tf32.tf32.f32 "
        "{%0,%1,%2,%3}, {%4,%5,%6,%7}, {%8,%9}, {%0,%1,%2,%3};"
        : "+f"(d[0]), "+f"(d[1]), "+f"(d[2]), "+f"(d[3])
        : "r"(a[0]), "r"(a[1]), "r"(a[2]), "r"(a[3]), "r"(b[0]), "r"(b[1]));
}

__device__ __forceinline__ void cpa16(uint32_t dst, const void* src) {
    asm volatile("cp.async.cg.shared.global [%0], [%1], 16;" :: "r"(dst), "l"(src));
}
__device__ __forceinline__ void cp_commit() {
    asm volatile("cp.async.commit_group;" ::: "memory");
}
__device__ __forceinline__ void cp_wait1() {
    asm volatile("cp.async.wait_group 1;" ::: "memory");
}
__device__ __forceinline__ void cp_wait0() {
    asm volatile("cp.async.wait_group 0;" ::: "memory");
}

// ---------------- GEMM: C[M,1024] = A[M,1024] @ W[1024,1024] + bias --------
// 128x128 tile, BK=32, 256 threads (8 warps), warp tile 64x32. R8 structure.
// ATF: A operand already tf32 bits (skip cvt). OTF: write output as tf32 bits.
#define GBM 128
#define GBN 128
#define GBK 32
#define ASTR 36
#define WSTR 136
#define ASTG (GBM*ASTR)       // 4608 words / stage
#define WSTG (GBK*WSTR)       // 4352 words / stage
#define GSM  (2*(ASTG+WSTG))  // 17920 words = 71680 B

template<int ATF, int OTF>
__global__ __launch_bounds__(256, 2) void gemm_tc(
    const float* __restrict__ A, const float* __restrict__ W,
    const float* __restrict__ bias, float* __restrict__ C, int split)
{
    extern __shared__ float smf[];
    float* Asb = smf;                 // 2 stages [128][36]
    float* Wsb = smf + 2 * ASTG;      // 2 stages [32][136]

    const int tid  = threadIdx.x;
    const int lane = tid & 31, warp = tid >> 5;
    const int g = lane >> 2, tg = lane & 3;
    const int wm = warp >> 2, wn = warp & 3;
    const int bm = blockIdx.y * GBM, bn = blockIdx.x * GBN;

    const int ar = tid >> 1;                 // A row 0..127
    const int ac = (tid & 1) * 16;           // A col word base
    const int wr = tid >> 3;                 // W row 0..31
    const int wc = (tid & 7) * 16;           // W col word base
    const float* Ab = A + (size_t)(bm + ar) * Ec + ac;
    const float* Wb = W + (size_t)wr * Ec + bn + wc;

    const uint32_t asA = (uint32_t)__cvta_generic_to_shared(Asb) + (ar * ASTR + ac) * 4;
    const uint32_t asW = (uint32_t)__cvta_generic_to_shared(Wsb) + (wr * WSTR + wc) * 4;

    float acc[4][4][4];
    #pragma unroll
    for (int mt = 0; mt < 4; mt++)
        #pragma unroll
        for (int nt = 0; nt < 4; nt++)
            #pragma unroll
            for (int i = 0; i < 4; i++) acc[mt][nt][i] = 0.f;

    #pragma unroll
    for (int j = 0; j < 4; j++) cpa16(asA + 16 * j, Ab + 4 * j);
    #pragma unroll
    for (int j = 0; j < 4; j++) cpa16(asW + 16 * j, Wb + 4 * j);
    cp_commit();

    const int NIT = Ec / GBK;   // 32
    for (int it = 0; it < NIT; it++) {
        const int p = it & 1;
        if (it + 1 < NIT) {
            const int k0 = (it + 1) * GBK;
            const uint32_t dA = asA + (1 - p) * ASTG * 4;
            const uint32_t dW = asW + (1 - p) * WSTG * 4;
            #pragma unroll
            for (int j = 0; j < 4; j++) cpa16(dA + 16 * j, Ab + k0 + 4 * j);
            #pragma unroll
            for (int j = 0; j < 4; j++) cpa16(dW + 16 * j, Wb + (size_t)k0 * Ec + 4 * j);
            cp_commit();
            cp_wait1();
        } else {
            cp_wait0();
        }
        __syncthreads();

        const float*    As  = Asb + p * ASTG;
        const uint32_t* Asu = (const uint32_t*)As;
        const float*    Ws  = Wsb + p * WSTG;

        #pragma unroll
        for (int ks = 0; ks < 4; ks++) {
            uint32_t af[4][4], bf[4][2];
            #pragma unroll
            for (int mt = 0; mt < 4; mt++) {
                const int r = wm * 64 + mt * 16 + g;
                if (ATF) {
                    af[mt][0] = Asu[r * ASTR + ks * 8 + tg];
                    af[mt][1] = Asu[(r + 8) * ASTR + ks * 8 + tg];
                    af[mt][2] = Asu[r * ASTR + ks * 8 + tg + 4];
                    af[mt][3] = Asu[(r + 8) * ASTR + ks * 8 + tg + 4];
                } else {
                    af[mt][0] = f2tf(As[r * ASTR + ks * 8 + tg]);
                    af[mt][1] = f2tf(As[(r + 8) * ASTR + ks * 8 + tg]);
                    af[mt][2] = f2tf(As[r * ASTR + ks * 8 + tg + 4]);
                    af[mt][3] = f2tf(As[(r + 8) * ASTR + ks * 8 + tg + 4]);
                }
            }
            #pragma unroll
            for (int nt = 0; nt < 4; nt++) {
                const int cb = wn * 32 + nt * 8 + g;
                bf[nt][0] = f2tf(Ws[(ks * 8 + tg) * WSTR + cb]);
                bf[nt][1] = f2tf(Ws[(ks * 8 + tg + 4) * WSTR + cb]);
            }
            #pragma unroll
            for (int mt = 0; mt < 4; mt++)
                #pragma unroll
                for (int nt = 0; nt < 4; nt++)
                    mma8(acc[mt][nt], af[mt], bf[nt]);
        }
        __syncthreads();
    }

    #pragma unroll
    for (int mt = 0; mt < 4; mt++) {
        #pragma unroll
        for (int half = 0; half < 2; half++) {
            const int m = bm + wm * 64 + mt * 16 + g + half * 8;
            #pragma unroll
            for (int nt = 0; nt < 4; nt++) {
                const int n = bn + wn * 32 + nt * 8 + 2 * tg;
                float2 bb = *(const float2*)&bias[n];
                float v0 = acc[mt][nt][half * 2 + 0] + bb.x;
                float v1 = acc[mt][nt][half * 2 + 1] + bb.y;
                if (OTF) {   // store as tf32 bit patterns
                    v0 = __uint_as_float(f2tf(v0));
                    v1 = __uint_as_float(f2tf(v1));
                }
                if (split) {
                    const int b = m >> 11, s = m & 2047;
                    const int h = n >> 6, d = n & 63;
                    *(float2*)&C[(((size_t)(b * Hc + h)) * Sc + s) * Dc + d] =
                        make_float2(v0, v1);
                } else {
                    *(float2*)&C[(size_t)m * Ec + n] = make_float2(v0, v1);
                }
            }
        }
    }
}

// ---------------- Flash attention (tf32 mma, P in regs, cp.async) ----------
// Inputs g_Q/g_K/g_V are ALREADY tf32 bits: fragments load with zero cvt.
// 128 q / CTA, 8 warps. S-MMA B rows permuted by pi(n)=(n>>1)+4(n&1) so the
// S accumulator is directly the PV A-fragment (P never stored).
#define AQ 128
#define QST 68
#define KST 68
#define VST 72
#define KSTG (64*KST)   // 4352
#define VSTG (64*VST)   // 4608
#define ASM_W (128*QST + 2*KSTG + 2*VSTG)   // 26624 words = 106496 B

__global__ __launch_bounds__(256, 2) void attn_tc(
    const float* __restrict__ Qg_, const float* __restrict__ Kg_,
    const float* __restrict__ Vg_, float* __restrict__ Ag_)
{
    extern __shared__ float smf[];
    float* Qs = smf;                       // [128][68]
    float* Kb = smf + 128 * QST;           // 2 x [64][68]
    float* Vb = Kb + 2 * KSTG;             // 2 x [64][72]

    const int tid  = threadIdx.x;
    const int lane = tid & 31, warp = tid >> 5;
    const int g = lane >> 2, tg = lane & 3;
    const int q0 = warp * 16;
    const int pig = (g >> 1) + 4 * (g & 1);

    const int qt = blockIdx.x, h = blockIdx.y, b = blockIdx.z;
    const size_t headOff = ((size_t)(b * Hc + h)) * Sc * Dc;
    const float* Qg = Qg_ + headOff + (size_t)qt * AQ * Dc;
    const float* Kg = Kg_ + headOff;
    const float* Vg = Vg_ + headOff;

    const int qr = tid >> 1, qc = (tid & 1) * 32;          // Q: 8 chunks
    const int kr = tid >> 2, kc = (tid & 3) * 16;          // K/V: 4 chunks
    const uint32_t sQ = (uint32_t)__cvta_generic_to_shared(Qs) + (qr * QST + qc) * 4;
    const uint32_t sK = (uint32_t)__cvta_generic_to_shared(Kb) + (kr * KST + kc) * 4;
    const uint32_t sV = (uint32_t)__cvta_generic_to_shared(Vb) + (kr * VST + kc) * 4;
    const float* Kgr = Kg + (size_t)kr * Dc + kc;
    const float* Vgr = Vg + (size_t)kr * Dc + kc;

    // prologue: Q + tile 0 (one group)
    #pragma unroll
    for (int j = 0; j < 8; j++) cpa16(sQ + 16 * j, Qg + (size_t)qr * Dc + qc + 4 * j);
    #pragma unroll
    for (int j = 0; j < 4; j++) cpa16(sK + 16 * j, Kgr + 4 * j);
    #pragma unroll
    for (int j = 0; j < 4; j++) cpa16(sV + 16 * j, Vgr + 4 * j);
    cp_commit();

    float o[8][4];
    float mrow[2], lrow[2];
    #pragma unroll
    for (int nt = 0; nt < 8; nt++)
        #pragma unroll
        for (int i = 0; i < 4; i++) o[nt][i] = 0.f;
    mrow[0] = mrow[1] = -INFINITY;
    lrow[0] = lrow[1] = 0.f;

    const int NT = Sc / 64;   // 32
    for (int kt = 0; kt < NT; kt++) {
        const int p = kt & 1;
        if (kt + 1 < NT) {
            const size_t off = (size_t)(kt + 1) * 64 * Dc;
            const uint32_t dK = sK + (1 - p) * KSTG * 4;
            const uint32_t dV = sV + (1 - p) * VSTG * 4;
            #pragma unroll
            for (int j = 0; j < 4; j++) cpa16(dK + 16 * j, Kgr + off + 4 * j);
            #pragma unroll
            for (int j = 0; j < 4; j++) cpa16(dV + 16 * j, Vgr + off + 4 * j);
            cp_commit();
            cp_wait1();
        } else {
            cp_wait0();
        }
        __syncthreads();

        const uint32_t* Qu = (const uint32_t*)Qs;
        const uint32_t* Ks = (const uint32_t*)(Kb + p * KSTG);
        const uint32_t* Vs = (const uint32_t*)(Vb + p * VSTG);

        // S = Q K^T (B rows taken at 8nt + pig), zero cvt
        float s[8][4];
        #pragma unroll
        for (int nt = 0; nt < 8; nt++)
            #pragma unroll
            for (int i = 0; i < 4; i++) s[nt][i] = 0.f;

        #pragma unroll
        for (int ks = 0; ks < 8; ks++) {
            uint32_t af[4];
            af[0] = Qu[(q0 + g) * QST + ks * 8 + tg];
            af[1] = Qu[(q0 + 8 + g) * QST + ks * 8 + tg];
            af[2] = Qu[(q0 + g) * QST + ks * 8 + tg + 4];
            af[3] = Qu[(q0 + 8 + g) * QST + ks * 8 + tg + 4];
            #pragma unroll
            for (int nt = 0; nt < 8; nt++) {
                const uint32_t* kp = Ks + (nt * 8 + pig) * KST;
                uint32_t bf[2];
                bf[0] = kp[ks * 8 + tg];
                bf[1] = kp[ks * 8 + tg + 4];
                mma8(s[nt], af, bf);
            }
        }

        // Online softmax (scale 0.125 here; rows spread over 4-lane quad)
        #pragma unroll
        for (int half = 0; half < 2; half++) {
            float tmax = -INFINITY;
            #pragma unroll
            for (int nt = 0; nt < 8; nt++) {
                s[nt][half * 2 + 0] *= 0.125f;
                s[nt][half * 2 + 1] *= 0.125f;
                tmax = fmaxf(tmax, s[nt][half * 2 + 0]);
                tmax = fmaxf(tmax, s[nt][half * 2 + 1]);
            }
            tmax = fmaxf(tmax, __shfl_xor_sync(0xffffffffu, tmax, 1));
            tmax = fmaxf(tmax, __shfl_xor_sync(0xffffffffu, tmax, 2));
            const float mn   = fmaxf(mrow[half], tmax);
            const float corr = __expf(mrow[half] - mn);
            float rs = 0.f;
            #pragma unroll
            for (int nt = 0; nt < 8; nt++) {
                float p0 = __expf(s[nt][half * 2 + 0] - mn);
                float p1 = __expf(s[nt][half * 2 + 1] - mn);
                s[nt][half * 2 + 0] = p0;
                s[nt][half * 2 + 1] = p1;
                rs += p0 + p1;
                o[nt][half * 2 + 0] *= corr;
                o[nt][half * 2 + 1] *= corr;
            }
            rs += __shfl_xor_sync(0xffffffffu, rs, 1);
            rs += __shfl_xor_sync(0xffffffffu, rs, 2);
            lrow[half] = lrow[half] * corr + rs;
            mrow[half] = mn;
        }

        // O += P @ V : P fragments straight from S accumulator (32 cvt only)
        #pragma unroll
        for (int ks = 0; ks < 8; ks++) {
            uint32_t af[4];
            af[0] = f2tf(s[ks][0]);
            af[1] = f2tf(s[ks][2]);
            af[2] = f2tf(s[ks][1]);
            af[3] = f2tf(s[ks][3]);
            const uint32_t* v0 = Vs + (ks * 8 + tg) * VST;
            const uint32_t* v1 = Vs + (ks * 8 + tg + 4) * VST;
            #pragma unroll
            for (int nt = 0; nt < 8; nt++) {
                uint32_t bf[2];
                bf[0] = v0[nt * 8 + g];
                bf[1] = v1[nt * 8 + g];
                mma8(o[nt], af, bf);
            }
        }
        __syncthreads();   // all warps done with buf p before next prefetch overwrites it
    }

    // Epilogue: normalize, write concat layout [B,S,E] as tf32 bits (for Wo GEMM)
    #pragma unroll
    for (int half = 0; half < 2; half++) {
        const float inv = 1.f / lrow[half];
        const int q = qt * AQ + q0 + g + half * 8;
        #pragma unroll
        for (int nt = 0; nt < 8; nt++) {
            const int d = nt * 8 + 2 * tg;
            float2 w = make_float2(
                __uint_as_float(f2tf(o[nt][half * 2 + 0] * inv)),
                __uint_as_float(f2tf(o[nt][half * 2 + 1] * inv)));
            *(float2*)&Ag_[((size_t)b * Sc + q) * Ec + h * Dc + d] = w;
        }
    }
}

// ---------------------------------------------------------------------------
extern "C" void kernel_launch(void* const* d_in, const int* in_sizes, int n_in,
                              void* d_out, int out_size)
{
    const float* x  = (const float*)d_in[0];
    const float* Wq = (const float*)d_in[1];
    const float* bq = (const float*)d_in[2];
    const float* Wk = (const float*)d_in[3];
    const float* bk = (const float*)d_in[4];
    const float* Wv = (const float*)d_in[5];
    const float* bv = (const float*)d_in[6];
    const float* Wo = (const float*)d_in[7];
    const float* bo = (const float*)d_in[8];
    float* out = (float*)d_out;

    float *pQ, *pK, *pV, *pA;
    cudaGetSymbolAddress((void**)&pQ, g_Q);
    cudaGetSymbolAddress((void**)&pK, g_K);
    cudaGetSymbolAddress((void**)&pV, g_V);
    cudaGetSymbolAddress((void**)&pA, g_A);

    const int gemmSmem = GSM * 4;      // 71680 B
    const int attnSmem = ASM_W * 4;    // 106496 B
    cudaFuncSetAttribute(gemm_tc<0,1>, cudaFuncAttributeMaxDynamicSharedMemorySize, gemmSmem);
    cudaFuncSetAttribute(gemm_tc<1,0>, cudaFuncAttributeMaxDynamicSharedMemorySize, gemmSmem);
    cudaFuncSetAttribute(attn_tc, cudaFuncAttributeMaxDynamicSharedMemorySize, attnSmem);

    dim3 gg(Ec / GBN, Mtot / GBM);   // (8, 64)
    gemm_tc<0,1><<<gg, 256, gemmSmem>>>(x, Wq, bq, pQ, 1);
    gemm_tc<0,1><<<gg, 256, gemmSmem>>>(x, Wk, bk, pK, 1);
    gemm_tc<0,1><<<gg, 256, gemmSmem>>>(x, Wv, bv, pV, 1);
    attn_tc<<<dim3(Sc / AQ, Hc, Bc), 256, attnSmem>>>(pQ, pK, pV, pA);
    gemm_tc<1,0><<<gg, 256, gemmSmem>>>(pA, Wo, bo, out, 0);
}

// round 11
// speedup vs baseline: 1.3182x; 1.0083x over previous
#include <cuda_runtime.h>
#include <math.h>
#include <stdint.h>

#define Bc 4
#define Sc 2048
#define Ec 1024
#define Hc 16
#define Dc 64
#define Mtot (Bc*Sc)   // 8192

// Scratch (static device globals: allocation-free)
// All of these hold tf32 BIT PATTERNS stored as float.
__device__ float g_Q[(size_t)Bc*Hc*Sc*Dc];
__device__ float g_K[(size_t)Bc*Hc*Sc*Dc];
__device__ float g_V[(size_t)Bc*Hc*Sc*Dc];
__device__ float g_A[(size_t)Bc*Sc*Ec];
__device__ float g_X[(size_t)Mtot*Ec];        // x pre-converted
__device__ float g_Wq[(size_t)Ec*Ec];
__device__ float g_Wk[(size_t)Ec*Ec];
__device__ float g_Wv[(size_t)Ec*Ec];
__device__ float g_Wo[(size_t)Ec*Ec];

// ---- helpers --------------------------------------------------------------
__device__ __forceinline__ uint32_t f2tf(float x) {
    uint32_t u;
    asm("cvt.rna.tf32.f32 %0, %1;" : "=r"(u) : "f"(x));
    return u;
}

__device__ __forceinline__ void mma8(float* d, const uint32_t* a, const uint32_t* b) {
    asm volatile(
        "mma.sync.aligned.m16n8k8.row.col.f32.tf32.tf32.f32 "
        "{%0,%1,%2,%3}, {%4,%5,%6,%7}, {%8,%9}, {%0,%1,%2,%3};"
        : "+f"(d[0]), "+f"(d[1]), "+f"(d[2]), "+f"(d[3])
        : "r"(a[0]), "r"(a[1]), "r"(a[2]), "r"(a[3]), "r"(b[0]), "r"(b[1]));
}

__device__ __forceinline__ void cpa16(uint32_t dst, const void* src) {
    asm volatile("cp.async.cg.shared.global [%0], [%1], 16;" :: "r"(dst), "l"(src));
}
__device__ __forceinline__ void cp_commit() {
    asm volatile("cp.async.commit_group;" ::: "memory");
}
__device__ __forceinline__ void cp_wait1() {
    asm volatile("cp.async.wait_group 1;" ::: "memory");
}
__device__ __forceinline__ void cp_wait0() {
    asm volatile("cp.async.wait_group 0;" ::: "memory");
}

// ---- pre-convert: out[i] = tf32_bits(in[i]), vectorized ------------------
__global__ __launch_bounds__(256) void cvt_tf32(
    const float* __restrict__ in, float* __restrict__ out, int n4)
{
    const int i = blockIdx.x * 256 + threadIdx.x;
    if (i < n4) {
        float4 v = ((const float4*)in)[i];
        uint4 u = make_uint4(f2tf(v.x), f2tf(v.y), f2tf(v.z), f2tf(v.w));
        ((uint4*)out)[i] = u;
    }
}

// ---------------- GEMM: C[M,1024] = A[M,1024] @ W[1024,1024] + bias --------
// 128x128 tile, BK=32, 256 threads (8 warps), warp tile 64x32. R8 structure.
// A and W are ALREADY tf32 bits; mainloop has ZERO cvt instructions.
// OTF: write output as tf32 bits (for downstream tensor-core consumer).
#define GBM 128
#define GBN 128
#define GBK 32
#define ASTR 36
#define WSTR 136
#define ASTG (GBM*ASTR)       // 4608 words / stage
#define WSTG (GBK*WSTR)       // 4352 words / stage
#define GSM  (2*(ASTG+WSTG))  // 17920 words = 71680 B

template<int OTF>
__global__ __launch_bounds__(256, 2) void gemm_tc(
    const float* __restrict__ A, const float* __restrict__ W,
    const float* __restrict__ bias, float* __restrict__ C, int split)
{
    extern __shared__ float smf[];
    float* Asb = smf;                 // 2 stages [128][36]
    float* Wsb = smf + 2 * ASTG;      // 2 stages [32][136]

    const int tid  = threadIdx.x;
    const int lane = tid & 31, warp = tid >> 5;
    const int g = lane >> 2, tg = lane & 3;
    const int wm = warp >> 2, wn = warp & 3;
    const int bm = blockIdx.y * GBM, bn = blockIdx.x * GBN;

    const int ar = tid >> 1;                 // A row 0..127
    const int ac = (tid & 1) * 16;           // A col word base
    const int wr = tid >> 3;                 // W row 0..31
    const int wc = (tid & 7) * 16;           // W col word base
    const float* Ab = A + (size_t)(bm + ar) * Ec + ac;
    const float* Wb = W + (size_t)wr * Ec + bn + wc;

    const uint32_t asA = (uint32_t)__cvta_generic_to_shared(Asb) + (ar * ASTR + ac) * 4;
    const uint32_t asW = (uint32_t)__cvta_generic_to_shared(Wsb) + (wr * WSTR + wc) * 4;

    float acc[4][4][4];
    #pragma unroll
    for (int mt = 0; mt < 4; mt++)
        #pragma unroll
        for (int nt = 0; nt < 4; nt++)
            #pragma unroll
            for (int i = 0; i < 4; i++) acc[mt][nt][i] = 0.f;

    #pragma unroll
    for (int j = 0; j < 4; j++) cpa16(asA + 16 * j, Ab + 4 * j);
    #pragma unroll
    for (int j = 0; j < 4; j++) cpa16(asW + 16 * j, Wb + 4 * j);
    cp_commit();

    const int NIT = Ec / GBK;   // 32
    for (int it = 0; it < NIT; it++) {
        const int p = it & 1;
        if (it + 1 < NIT) {
            const int k0 = (it + 1) * GBK;
            const uint32_t dA = asA + (1 - p) * ASTG * 4;
            const uint32_t dW = asW + (1 - p) * WSTG * 4;
            #pragma unroll
            for (int j = 0; j < 4; j++) cpa16(dA + 16 * j, Ab + k0 + 4 * j);
            #pragma unroll
            for (int j = 0; j < 4; j++) cpa16(dW + 16 * j, Wb + (size_t)k0 * Ec + 4 * j);
            cp_commit();
            cp_wait1();
        } else {
            cp_wait0();
        }
        __syncthreads();

        const uint32_t* As = (const uint32_t*)(Asb + p * ASTG);
        const uint32_t* Ws = (const uint32_t*)(Wsb + p * WSTG);

        #pragma unroll
        for (int ks = 0; ks < 4; ks++) {
            uint32_t af[4][4], bf[4][2];
            #pragma unroll
            for (int mt = 0; mt < 4; mt++) {
                const int r = wm * 64 + mt * 16 + g;
                af[mt][0] = As[r * ASTR + ks * 8 + tg];
                af[mt][1] = As[(r + 8) * ASTR + ks * 8 + tg];
                af[mt][2] = As[r * ASTR + ks * 8 + tg + 4];
                af[mt][3] = As[(r + 8) * ASTR + ks * 8 + tg + 4];
            }
            #pragma unroll
            for (int nt = 0; nt < 4; nt++) {
                const int cb = wn * 32 + nt * 8 + g;
                bf[nt][0] = Ws[(ks * 8 + tg) * WSTR + cb];
                bf[nt][1] = Ws[(ks * 8 + tg + 4) * WSTR + cb];
            }
            #pragma unroll
            for (int mt = 0; mt < 4; mt++)
                #pragma unroll
                for (int nt = 0; nt < 4; nt++)
                    mma8(acc[mt][nt], af[mt], bf[nt]);
        }
        __syncthreads();
    }

    #pragma unroll
    for (int mt = 0; mt < 4; mt++) {
        #pragma unroll
        for (int half = 0; half < 2; half++) {
            const int m = bm + wm * 64 + mt * 16 + g + half * 8;
            #pragma unroll
            for (int nt = 0; nt < 4; nt++) {
                const int n = bn + wn * 32 + nt * 8 + 2 * tg;
                float2 bb = *(const float2*)&bias[n];
                float v0 = acc[mt][nt][half * 2 + 0] + bb.x;
                float v1 = acc[mt][nt][half * 2 + 1] + bb.y;
                if (OTF) {   // store as tf32 bit patterns
                    v0 = __uint_as_float(f2tf(v0));
                    v1 = __uint_as_float(f2tf(v1));
                }
                if (split) {
                    const int b = m >> 11, s = m & 2047;
                    const int h = n >> 6, d = n & 63;
                    *(float2*)&C[(((size_t)(b * Hc + h)) * Sc + s) * Dc + d] =
                        make_float2(v0, v1);
                } else {
                    *(float2*)&C[(size_t)m * Ec + n] = make_float2(v0, v1);
                }
            }
        }
    }
}

// ---------------- Flash attention (tf32 mma, P in regs, cp.async) ----------
// Inputs g_Q/g_K/g_V are ALREADY tf32 bits: fragments load with zero cvt.
// 128 q / CTA, 8 warps. S-MMA B rows permuted by pi(n)=(n>>1)+4(n&1) so the
// S accumulator is directly the PV A-fragment (P never stored).
#define AQ 128
#define QST 68
#define KST 68
#define VST 72
#define KSTG (64*KST)   // 4352
#define VSTG (64*VST)   // 4608
#define ASM_W (128*QST + 2*KSTG + 2*VSTG)   // 26624 words = 106496 B

__global__ __launch_bounds__(256, 2) void attn_tc(
    const float* __restrict__ Qg_, const float* __restrict__ Kg_,
    const float* __restrict__ Vg_, float* __restrict__ Ag_)
{
    extern __shared__ float smf[];
    float* Qs = smf;                       // [128][68]
    float* Kb = smf + 128 * QST;           // 2 x [64][68]
    float* Vb = Kb + 2 * KSTG;             // 2 x [64][72]

    const int tid  = threadIdx.x;
    const int lane = tid & 31, warp = tid >> 5;
    const int g = lane >> 2, tg = lane & 3;
    const int q0 = warp * 16;
    const int pig = (g >> 1) + 4 * (g & 1);

    const int qt = blockIdx.x, h = blockIdx.y, b = blockIdx.z;
    const size_t headOff = ((size_t)(b * Hc + h)) * Sc * Dc;
    const float* Qg = Qg_ + headOff + (size_t)qt * AQ * Dc;
    const float* Kg = Kg_ + headOff;
    const float* Vg = Vg_ + headOff;

    const int qr = tid >> 1, qc = (tid & 1) * 32;          // Q: 8 chunks
    const int kr = tid >> 2, kc = (tid & 3) * 16;          // K/V: 4 chunks
    const uint32_t sQ = (uint32_t)__cvta_generic_to_shared(Qs) + (qr * QST + qc) * 4;
    const uint32_t sK = (uint32_t)__cvta_generic_to_shared(Kb) + (kr * KST + kc) * 4;
    const uint32_t sV = (uint32_t)__cvta_generic_to_shared(Vb) + (kr * VST + kc) * 4;
    const float* Kgr = Kg + (size_t)kr * Dc + kc;
    const float* Vgr = Vg + (size_t)kr * Dc + kc;

    // prologue: Q + tile 0 (one group)
    #pragma unroll
    for (int j = 0; j < 8; j++) cpa16(sQ + 16 * j, Qg + (size_t)qr * Dc + qc + 4 * j);
    #pragma unroll
    for (int j = 0; j < 4; j++) cpa16(sK + 16 * j, Kgr + 4 * j);
    #pragma unroll
    for (int j = 0; j < 4; j++) cpa16(sV + 16 * j, Vgr + 4 * j);
    cp_commit();

    float o[8][4];
    float mrow[2], lrow[2];
    #pragma unroll
    for (int nt = 0; nt < 8; nt++)
        #pragma unroll
        for (int i = 0; i < 4; i++) o[nt][i] = 0.f;
    mrow[0] = mrow[1] = -INFINITY;
    lrow[0] = lrow[1] = 0.f;

    const int NT = Sc / 64;   // 32
    for (int kt = 0; kt < NT; kt++) {
        const int p = kt & 1;
        if (kt + 1 < NT) {
            const size_t off = (size_t)(kt + 1) * 64 * Dc;
            const uint32_t dK = sK + (1 - p) * KSTG * 4;
            const uint32_t dV = sV + (1 - p) * VSTG * 4;
            #pragma unroll
            for (int j = 0; j < 4; j++) cpa16(dK + 16 * j, Kgr + off + 4 * j);
            #pragma unroll
            for (int j = 0; j < 4; j++) cpa16(dV + 16 * j, Vgr + off + 4 * j);
            cp_commit();
            cp_wait1();
        } else {
            cp_wait0();
        }
        __syncthreads();

        const uint32_t* Qu = (const uint32_t*)Qs;
        const uint32_t* Ks = (const uint32_t*)(Kb + p * KSTG);
        const uint32_t* Vs = (const uint32_t*)(Vb + p * VSTG);

        // S = Q K^T (B rows taken at 8nt + pig), zero cvt
        float s[8][4];
        #pragma unroll
        for (int nt = 0; nt < 8; nt++)
            #pragma unroll
            for (int i = 0; i < 4; i++) s[nt][i] = 0.f;

        #pragma unroll
        for (int ks = 0; ks < 8; ks++) {
            uint32_t af[4];
            af[0] = Qu[(q0 + g) * QST + ks * 8 + tg];
            af[1] = Qu[(q0 + 8 + g) * QST + ks * 8 + tg];
            af[2] = Qu[(q0 + g) * QST + ks * 8 + tg + 4];
            af[3] = Qu[(q0 + 8 + g) * QST + ks * 8 + tg + 4];
            #pragma unroll
            for (int nt = 0; nt < 8; nt++) {
                const uint32_t* kp = Ks + (nt * 8 + pig) * KST;
                uint32_t bf[2];
                bf[0] = kp[ks * 8 + tg];
                bf[1] = kp[ks * 8 + tg + 4];
                mma8(s[nt], af, bf);
            }
        }

        // Online softmax (scale 0.125 here; rows spread over 4-lane quad)
        #pragma unroll
        for (int half = 0; half < 2; half++) {
            float tmax = -INFINITY;
            #pragma unroll
            for (int nt = 0; nt < 8; nt++) {
                s[nt][half * 2 + 0] *= 0.125f;
                s[nt][half * 2 + 1] *= 0.125f;
                tmax = fmaxf(tmax, s[nt][half * 2 + 0]);
                tmax = fmaxf(tmax, s[nt][half * 2 + 1]);
            }
            tmax = fmaxf(tmax, __shfl_xor_sync(0xffffffffu, tmax, 1));
            tmax = fmaxf(tmax, __shfl_xor_sync(0xffffffffu, tmax, 2));
            const float mn   = fmaxf(mrow[half], tmax);
            const float corr = __expf(mrow[half] - mn);
            float rs = 0.f;
            #pragma unroll
            for (int nt = 0; nt < 8; nt++) {
                float p0 = __expf(s[nt][half * 2 + 0] - mn);
                float p1 = __expf(s[nt][half * 2 + 1] - mn);
                s[nt][half * 2 + 0] = p0;
                s[nt][half * 2 + 1] = p1;
                rs += p0 + p1;
                o[nt][half * 2 + 0] *= corr;
                o[nt][half * 2 + 1] *= corr;
            }
            rs += __shfl_xor_sync(0xffffffffu, rs, 1);
            rs += __shfl_xor_sync(0xffffffffu, rs, 2);
            lrow[half] = lrow[half] * corr + rs;
            mrow[half] = mn;
        }

        // O += P @ V : P fragments straight from S accumulator (32 cvt only)
        #pragma unroll
        for (int ks = 0; ks < 8; ks++) {
            uint32_t af[4];
            af[0] = f2tf(s[ks][0]);
            af[1] = f2tf(s[ks][2]);
            af[2] = f2tf(s[ks][1]);
            af[3] = f2tf(s[ks][3]);
            const uint32_t* v0 = Vs + (ks * 8 + tg) * VST;
            const uint32_t* v1 = Vs + (ks * 8 + tg + 4) * VST;
            #pragma unroll
            for (int nt = 0; nt < 8; nt++) {
                uint32_t bf[2];
                bf[0] = v0[nt * 8 + g];
                bf[1] = v1[nt * 8 + g];
                mma8(o[nt], af, bf);
            }
        }
        __syncthreads();   // all warps done with buf p before next prefetch overwrites it
    }

    // Epilogue: normalize, write concat layout [B,S,E] as tf32 bits (for Wo GEMM)
    #pragma unroll
    for (int half = 0; half < 2; half++) {
        const float inv = 1.f / lrow[half];
        const int q = qt * AQ + q0 + g + half * 8;
        #pragma unroll
        for (int nt = 0; nt < 8; nt++) {
            const int d = nt * 8 + 2 * tg;
            float2 w = make_float2(
                __uint_as_float(f2tf(o[nt][half * 2 + 0] * inv)),
                __uint_as_float(f2tf(o[nt][half * 2 + 1] * inv)));
            *(float2*)&Ag_[((size_t)b * Sc + q) * Ec + h * Dc + d] = w;
        }
    }
}

// ---------------------------------------------------------------------------
extern "C" void kernel_launch(void* const* d_in, const int* in_sizes, int n_in,
                              void* d_out, int out_size)
{
    const float* x  = (const float*)d_in[0];
    const float* Wq = (const float*)d_in[1];
    const float* bq = (const float*)d_in[2];
    const float* Wk = (const float*)d_in[3];
    const float* bk = (const float*)d_in[4];
    const float* Wv = (const float*)d_in[5];
    const float* bv = (const float*)d_in[6];
    const float* Wo = (const float*)d_in[7];
    const float* bo = (const float*)d_in[8];
    float* out = (float*)d_out;

    float *pQ, *pK, *pV, *pA, *pX, *pWq, *pWk, *pWv, *pWo;
    cudaGetSymbolAddress((void**)&pQ, g_Q);
    cudaGetSymbolAddress((void**)&pK, g_K);
    cudaGetSymbolAddress((void**)&pV, g_V);
    cudaGetSymbolAddress((void**)&pA, g_A);
    cudaGetSymbolAddress((void**)&pX, g_X);
    cudaGetSymbolAddress((void**)&pWq, g_Wq);
    cudaGetSymbolAddress((void**)&pWk, g_Wk);
    cudaGetSymbolAddress((void**)&pWv, g_Wv);
    cudaGetSymbolAddress((void**)&pWo, g_Wo);

    const int gemmSmem = GSM * 4;      // 71680 B
    const int attnSmem = ASM_W * 4;    // 106496 B
    cudaFuncSetAttribute(gemm_tc<0>, cudaFuncAttributeMaxDynamicSharedMemorySize, gemmSmem);
    cudaFuncSetAttribute(gemm_tc<1>, cudaFuncAttributeMaxDynamicSharedMemorySize, gemmSmem);
    cudaFuncSetAttribute(attn_tc, cudaFuncAttributeMaxDynamicSharedMemorySize, attnSmem);

    // pre-convert x and all weights to tf32 bit patterns
    const int xN4 = Mtot * Ec / 4;   // 2097152
    const int wN4 = Ec * Ec / 4;     // 262144
    cvt_tf32<<<(xN4 + 255) / 256, 256>>>(x, pX, xN4);
    cvt_tf32<<<(wN4 + 255) / 256, 256>>>(Wq, pWq, wN4);
    cvt_tf32<<<(wN4 + 255) / 256, 256>>>(Wk, pWk, wN4);
    cvt_tf32<<<(wN4 + 255) / 256, 256>>>(Wv, pWv, wN4);
    cvt_tf32<<<(wN4 + 255) / 256, 256>>>(Wo, pWo, wN4);

    dim3 gg(Ec / GBN, Mtot / GBM);   // (8, 64)
    gemm_tc<1><<<gg, 256, gemmSmem>>>(pX, pWq, bq, pQ, 1);
    gemm_tc<1><<<gg, 256, gemmSmem>>>(pX, pWk, bk, pK, 1);
    gemm_tc<1><<<gg, 256, gemmSmem>>>(pX, pWv, bv, pV, 1);
    attn_tc<<<dim3(Sc / AQ, Hc, Bc), 256, attnSmem>>>(pQ, pK, pV, pA);
    gemm_tc<0><<<gg, 256, gemmSmem>>>(pA, pWo, bo, out, 0);
}

// round 12
// speedup vs baseline: 2.0334x; 1.5425x over previous
#include <cuda_runtime.h>
#include <cuda.h>
#include <math.h>
#include <stdint.h>

#define Bc 4
#define Sc 2048
#define Ec 1024
#define Hc 16
#define Dc 64
#define Mtot (Bc*Sc)   // 8192

// Scratch (static device globals: allocation-free). All hold tf32 bit patterns.
__device__ float g_Q[(size_t)Bc*Hc*Sc*Dc];
__device__ float g_K[(size_t)Bc*Hc*Sc*Dc];
__device__ float g_V[(size_t)Bc*Hc*Sc*Dc];
__device__ float g_A[(size_t)Bc*Sc*Ec];
__device__ float g_X[(size_t)Mtot*Ec];
__device__ float g_Wq[(size_t)Ec*Ec];   // TRANSPOSED [n][k]
__device__ float g_Wk[(size_t)Ec*Ec];   // TRANSPOSED
__device__ float g_Wv[(size_t)Ec*Ec];   // TRANSPOSED
__device__ float g_Wo[(size_t)Ec*Ec];   // TRANSPOSED

// ---- helpers --------------------------------------------------------------
__device__ __forceinline__ uint32_t f2tf(float x) {
    uint32_t u;
    asm("cvt.rna.tf32.f32 %0, %1;" : "=r"(u) : "f"(x));
    return u;
}

__device__ __forceinline__ void mma8(float* d, const uint32_t* a, const uint32_t* b) {
    asm volatile(
        "mma.sync.aligned.m16n8k8.row.col.f32.tf32.tf32.f32 "
        "{%0,%1,%2,%3}, {%4,%5,%6,%7}, {%8,%9}, {%0,%1,%2,%3};"
        : "+f"(d[0]), "+f"(d[1]), "+f"(d[2]), "+f"(d[3])
        : "r"(a[0]), "r"(a[1]), "r"(a[2]), "r"(a[3]), "r"(b[0]), "r"(b[1]));
}

__device__ __forceinline__ void cpa16(uint32_t dst, const void* src) {
    asm volatile("cp.async.cg.shared.global [%0], [%1], 16;" :: "r"(dst), "l"(src));
}
__device__ __forceinline__ void cp_commit() {
    asm volatile("cp.async.commit_group;" ::: "memory");
}
__device__ __forceinline__ void cp_wait0() {
    asm volatile("cp.async.wait_group 0;" ::: "memory");
}

__device__ __forceinline__ void mbar_init(uint32_t a, uint32_t cnt) {
    asm volatile("mbarrier.init.shared.b64 [%0], %1;" :: "r"(a), "r"(cnt) : "memory");
}
__device__ __forceinline__ void mbar_expect(uint32_t a, uint32_t bytes) {
    asm volatile("mbarrier.arrive.expect_tx.shared.b64 _, [%0], %1;"
                 :: "r"(a), "r"(bytes) : "memory");
}
__device__ __forceinline__ void mbar_wait(uint32_t a, uint32_t par) {
    asm volatile(
        "{\n\t.reg .pred P;\n\t"
        "LW%=:\n\t"
        "mbarrier.try_wait.parity.acquire.cta.shared::cta.b64 P, [%0], %1, 0x989680;\n\t"
        "@P bra LD%=;\n\t"
        "bra LW%=;\n\t"
        "LD%=:\n\t}"
        :: "r"(a), "r"(par) : "memory");
}
__device__ __forceinline__ void tma2d(uint32_t dst, const CUtensorMap* m,
                                      int x, int y, uint32_t mb) {
    asm volatile(
        "cp.async.bulk.tensor.2d.shared::cta.global.tile.mbarrier::complete_tx::bytes "
        "[%0], [%1, {%2, %3}], [%4];"
        :: "r"(dst), "l"(m), "r"(x), "r"(y), "r"(mb) : "memory");
}
__device__ __forceinline__ void tma3d(uint32_t dst, const CUtensorMap* m,
                                      int x, int y, int z, uint32_t mb) {
    asm volatile(
        "cp.async.bulk.tensor.3d.shared::cta.global.tile.mbarrier::complete_tx::bytes "
        "[%0], [%1, {%2, %3, %4}], [%5];"
        :: "r"(dst), "l"(m), "r"(x), "r"(y), "r"(z), "r"(mb) : "memory");
}

// ---- pre-convert kernels --------------------------------------------------
__global__ __launch_bounds__(256) void cvt_tf32(
    const float* __restrict__ in, float* __restrict__ out, int n4)
{
    const int i = blockIdx.x * 256 + threadIdx.x;
    if (i < n4) {
        float4 v = ((const float4*)in)[i];
        uint4 u = make_uint4(f2tf(v.x), f2tf(v.y), f2tf(v.z), f2tf(v.w));
        ((uint4*)out)[i] = u;
    }
}

// transpose + convert: out[n][k] = tf32_bits(in[k][n]); 32x32 smem tiles
__global__ __launch_bounds__(256) void cvt_tr(
    const float* __restrict__ in, float* __restrict__ out)
{
    __shared__ float t[32][33];
    const int n0 = blockIdx.x * 32, k0 = blockIdx.y * 32;
    const int tx = threadIdx.x & 31, ty = threadIdx.x >> 5;   // 32 x 8
    #pragma unroll
    for (int j = 0; j < 4; j++)
        t[ty * 4 + j][tx] =
            __uint_as_float(f2tf(in[(size_t)(k0 + ty * 4 + j) * Ec + n0 + tx]));
    __syncthreads();
    #pragma unroll
    for (int j = 0; j < 4; j++)
        out[(size_t)(n0 + ty * 4 + j) * Ec + k0 + tx] = t[tx][ty * 4 + j];
}

// ---------------- GEMM: C[M,1024] = A[M,1024] @ W + bias (TMA loads) -------
// A smem [128 m][32 k] SW128, W smem [128 n][32 k] SW128 (W pre-transposed).
// 128x128 tile, BK=32, 256 threads, warp tile 64x32, 2-stage mbarrier pipe.
#define GBM 128
#define GBN 128
#define GBK 32
#define GA0 0
#define GW0 32768
#define GMB 65536
#define GSMEM 65552

template<int OTF>
__global__ __launch_bounds__(256, 2) void gemm_tc(
    const __grid_constant__ CUtensorMap mA,
    const __grid_constant__ CUtensorMap mW,
    const float* __restrict__ bias, float* __restrict__ C, int split)
{
    extern __shared__ char smem[];
    uint32_t smb;
    asm("{ .reg .u64 t; cvta.to.shared.u64 t, %1; cvt.u32.u64 %0, t; }"
        : "=r"(smb) : "l"(smem));

    const int tid  = threadIdx.x;
    const int lane = tid & 31, warp = tid >> 5;
    const int g = lane >> 2, tg = lane & 3;
    const int wm = warp >> 2, wn = warp & 3;
    const int bm = blockIdx.y * GBM, bn = blockIdx.x * GBN;
    const int xg = 4 * g;   // SW128 word-col XOR for rows with row&7==g

    if (tid == 0) { mbar_init(smb + GMB, 1); mbar_init(smb + GMB + 8, 1); }
    __syncthreads();
    if (tid == 0) {
        mbar_expect(smb + GMB, 32768);
        tma2d(smb + GA0, &mA, 0, bm, smb + GMB);
        tma2d(smb + GW0, &mW, 0, bn, smb + GMB);
    }

    float acc[4][4][4];
    #pragma unroll
    for (int mt = 0; mt < 4; mt++)
        #pragma unroll
        for (int nt = 0; nt < 4; nt++)
            #pragma unroll
            for (int i = 0; i < 4; i++) acc[mt][nt][i] = 0.f;

    const int NIT = Ec / GBK;   // 32
    for (int it = 0; it < NIT; it++) {
        const int p = it & 1;
        if (it) __syncthreads();   // readers of stage 1-p are done
        if (tid == 0 && it + 1 < NIT) {
            const uint32_t mb = smb + GMB + 8 * (1 - p);
            mbar_expect(mb, 32768);
            tma2d(smb + GA0 + 16384 * (1 - p), &mA, (it + 1) * GBK, bm, mb);
            tma2d(smb + GW0 + 16384 * (1 - p), &mW, (it + 1) * GBK, bn, mb);
        }
        mbar_wait(smb + GMB + 8 * p, (it >> 1) & 1);

        const uint32_t* Au = (const uint32_t*)(smem + GA0 + 16384 * p);
        const uint32_t* Wu = (const uint32_t*)(smem + GW0 + 16384 * p);

        #pragma unroll
        for (int ks = 0; ks < 4; ks++) {
            const int c0 = (8 * ks + tg) ^ xg;
            const int c4 = (8 * ks + tg + 4) ^ xg;
            uint32_t af[4][4], bf[4][2];
            #pragma unroll
            for (int mt = 0; mt < 4; mt++) {
                const int r = wm * 64 + mt * 16 + g;
                af[mt][0] = Au[r * 32 + c0];
                af[mt][1] = Au[(r + 8) * 32 + c0];
                af[mt][2] = Au[r * 32 + c4];
                af[mt][3] = Au[(r + 8) * 32 + c4];
            }
            #pragma unroll
            for (int nt = 0; nt < 4; nt++) {
                const int cb = wn * 32 + nt * 8 + g;
                bf[nt][0] = Wu[cb * 32 + c0];
                bf[nt][1] = Wu[cb * 32 + c4];
            }
            #pragma unroll
            for (int mt = 0; mt < 4; mt++)
                #pragma unroll
                for (int nt = 0; nt < 4; nt++)
                    mma8(acc[mt][nt], af[mt], bf[nt]);
        }
    }

    #pragma unroll
    for (int mt = 0; mt < 4; mt++) {
        #pragma unroll
        for (int half = 0; half < 2; half++) {
            const int m = bm + wm * 64 + mt * 16 + g + half * 8;
            #pragma unroll
            for (int nt = 0; nt < 4; nt++) {
                const int n = bn + wn * 32 + nt * 8 + 2 * tg;
                float2 bb = *(const float2*)&bias[n];
                float v0 = acc[mt][nt][half * 2 + 0] + bb.x;
                float v1 = acc[mt][nt][half * 2 + 1] + bb.y;
                if (OTF) {
                    v0 = __uint_as_float(f2tf(v0));
                    v1 = __uint_as_float(f2tf(v1));
                }
                if (split) {
                    const int b = m >> 11, s = m & 2047;
                    const int h = n >> 6, d = n & 63;
                    *(float2*)&C[(((size_t)(b * Hc + h)) * Sc + s) * Dc + d] =
                        make_float2(v0, v1);
                } else {
                    *(float2*)&C[(size_t)m * Ec + n] = make_float2(v0, v1);
                }
            }
        }
    }
}

// ---------------- Flash attention (tf32 mma, P in regs, TMA K/V) -----------
// Q[128][68] via cp.async (once). K/V per tile via 3D TMA: 2 boxes of
// (32 d x 64 s), SW128, smem [2 blk][64 row][32 word]. S-MMA B rows permuted
// by pi so the S accumulator is directly the PV A-fragment.
#define AQ 128
#define QST 68
#define AQ0 0
#define AK0 34816
#define AV0 67584
#define AMB 100352
#define ASMEM 100368

__global__ __launch_bounds__(256, 2) void attn_tc(
    const float* __restrict__ Qg_, const float* __restrict__ Kg_,
    const float* __restrict__ Vg_, float* __restrict__ Ag_,
    const __grid_constant__ CUtensorMap mK,
    const __grid_constant__ CUtensorMap mV)
{
    extern __shared__ char smem[];
    uint32_t smb;
    asm("{ .reg .u64 t; cvta.to.shared.u64 t, %1; cvt.u32.u64 %0, t; }"
        : "=r"(smb) : "l"(smem));
    float* Qs = (float*)smem;   // [128][68]

    const int tid  = threadIdx.x;
    const int lane = tid & 31, warp = tid >> 5;
    const int g = lane >> 2, tg = lane & 3;
    const int q0 = warp * 16;
    const int pig = (g >> 1) + 4 * (g & 1);

    const int qt = blockIdx.x, h = blockIdx.y, b = blockIdx.z;
    const int bh = b * Hc + h;
    const float* Qg = Qg_ + ((size_t)bh * Sc + (size_t)qt * AQ) * Dc;

    if (tid == 0) { mbar_init(smb + AMB, 1); mbar_init(smb + AMB + 8, 1); }
    __syncthreads();

    // Q via cp.async (one-time); K/V tile 0 via TMA
    const int qr = tid >> 1, qc = (tid & 1) * 32;
    {
        const uint32_t sQ = smb + AQ0 + (qr * QST + qc) * 4;
        #pragma unroll
        for (int j = 0; j < 8; j++)
            cpa16(sQ + 16 * j, Qg + (size_t)qr * Dc + qc + 4 * j);
        cp_commit();
    }
    if (tid == 0) {
        mbar_expect(smb + AMB, 32768);
        tma3d(smb + AK0,        &mK,  0, 0, bh, smb + AMB);
        tma3d(smb + AK0 + 8192, &mK, 32, 0, bh, smb + AMB);
        tma3d(smb + AV0,        &mV,  0, 0, bh, smb + AMB);
        tma3d(smb + AV0 + 8192, &mV, 32, 0, bh, smb + AMB);
    }
    cp_wait0();
    __syncthreads();   // Q visible to all

    float o[8][4];
    float mrow[2], lrow[2];
    #pragma unroll
    for (int nt = 0; nt < 8; nt++)
        #pragma unroll
        for (int i = 0; i < 4; i++) o[nt][i] = 0.f;
    mrow[0] = mrow[1] = -INFINITY;
    lrow[0] = lrow[1] = 0.f;

    const uint32_t* Qu = (const uint32_t*)Qs;
    const int NT = Sc / 64;   // 32
    for (int kt = 0; kt < NT; kt++) {
        const int p = kt & 1;
        if (kt) __syncthreads();   // readers of stage 1-p done
        if (tid == 0 && kt + 1 < NT) {
            const uint32_t mb = smb + AMB + 8 * (1 - p);
            const int kv0 = (kt + 1) * 64;
            mbar_expect(mb, 32768);
            tma3d(smb + AK0 + 16384 * (1 - p),        &mK,  0, kv0, bh, mb);
            tma3d(smb + AK0 + 16384 * (1 - p) + 8192, &mK, 32, kv0, bh, mb);
            tma3d(smb + AV0 + 16384 * (1 - p),        &mV,  0, kv0, bh, mb);
            tma3d(smb + AV0 + 16384 * (1 - p) + 8192, &mV, 32, kv0, bh, mb);
        }
        mbar_wait(smb + AMB + 8 * p, (kt >> 1) & 1);

        const uint32_t* Ku = (const uint32_t*)(smem + AK0 + 16384 * p);
        const uint32_t* Vu = (const uint32_t*)(smem + AV0 + 16384 * p);

        // S = Q K^T (K rows taken at 8nt + pig)
        float s[8][4];
        #pragma unroll
        for (int nt = 0; nt < 8; nt++)
            #pragma unroll
            for (int i = 0; i < 4; i++) s[nt][i] = 0.f;

        #pragma unroll
        for (int ks = 0; ks < 8; ks++) {
            uint32_t af[4];
            af[0] = Qu[(q0 + g) * QST + ks * 8 + tg];
            af[1] = Qu[(q0 + 8 + g) * QST + ks * 8 + tg];
            af[2] = Qu[(q0 + g) * QST + ks * 8 + tg + 4];
            af[3] = Qu[(q0 + 8 + g) * QST + ks * 8 + tg + 4];
            // K smem: block = ks>>2; within: row kv, col (d&31)^(4*(kv&7))
            const int blk = (ks >> 2) * 2048;
            const int d0 = 8 * (ks & 3) + tg;
            const int xp = 4 * pig;
            #pragma unroll
            for (int nt = 0; nt < 8; nt++) {
                const int row = (8 * nt + pig) * 32;
                uint32_t bf[2];
                bf[0] = Ku[blk + row + (d0 ^ xp)];
                bf[1] = Ku[blk + row + ((d0 + 4) ^ xp)];
                mma8(s[nt], af, bf);
            }
        }

        // Online softmax (scale 0.125; rows spread over 4-lane quad)
        #pragma unroll
        for (int half = 0; half < 2; half++) {
            float tmax = -INFINITY;
            #pragma unroll
            for (int nt = 0; nt < 8; nt++) {
                s[nt][half * 2 + 0] *= 0.125f;
                s[nt][half * 2 + 1] *= 0.125f;
                tmax = fmaxf(tmax, s[nt][half * 2 + 0]);
                tmax = fmaxf(tmax, s[nt][half * 2 + 1]);
            }
            tmax = fmaxf(tmax, __shfl_xor_sync(0xffffffffu, tmax, 1));
            tmax = fmaxf(tmax, __shfl_xor_sync(0xffffffffu, tmax, 2));
            const float mn   = fmaxf(mrow[half], tmax);
            const float corr = __expf(mrow[half] - mn);
            float rs = 0.f;
            #pragma unroll
            for (int nt = 0; nt < 8; nt++) {
                float p0 = __expf(s[nt][half * 2 + 0] - mn);
                float p1 = __expf(s[nt][half * 2 + 1] - mn);
                s[nt][half * 2 + 0] = p0;
                s[nt][half * 2 + 1] = p1;
                rs += p0 + p1;
                o[nt][half * 2 + 0] *= corr;
                o[nt][half * 2 + 1] *= corr;
            }
            rs += __shfl_xor_sync(0xffffffffu, rs, 1);
            rs += __shfl_xor_sync(0xffffffffu, rs, 2);
            lrow[half] = lrow[half] * corr + rs;
            mrow[half] = mn;
        }

        // O += P @ V ; V smem: block = nt>>2; row kv = 8ks+tg (+4)
        #pragma unroll
        for (int ks = 0; ks < 8; ks++) {
            uint32_t af[4];
            af[0] = f2tf(s[ks][0]);
            af[1] = f2tf(s[ks][2]);
            af[2] = f2tf(s[ks][1]);
            af[3] = f2tf(s[ks][3]);
            const int r0 = (8 * ks + tg) * 32;
            const int r4 = (8 * ks + tg + 4) * 32;
            const int x0 = 4 * tg;
            const int x4 = 4 * tg + 16;   // 4*((tg+4)&7)
            #pragma unroll
            for (int nt = 0; nt < 8; nt++) {
                const int blk = (nt >> 2) * 2048;
                const int dc = (8 * nt + g) & 31;
                uint32_t bf[2];
                bf[0] = Vu[blk + r0 + (dc ^ x0)];
                bf[1] = Vu[blk + r4 + (dc ^ x4)];
                mma8(o[nt], af, bf);
            }
        }
    }

    // Epilogue: normalize, write concat [B,S,E] as tf32 bits (for Wo GEMM)
    #pragma unroll
    for (int half = 0; half < 2; half++) {
        const float inv = 1.f / lrow[half];
        const int q = qt * AQ + q0 + g + half * 8;
        #pragma unroll
        for (int nt = 0; nt < 8; nt++) {
            const int d = nt * 8 + 2 * tg;
            float2 w = make_float2(
                __uint_as_float(f2tf(o[nt][half * 2 + 0] * inv)),
                __uint_as_float(f2tf(o[nt][half * 2 + 1] * inv)));
            *(float2*)&Ag_[((size_t)b * Sc + q) * Ec + h * Dc + d] = w;
        }
    }
}

// ---------------------------------------------------------------------------
typedef CUresult (*PFN_tmencode)(
    CUtensorMap*, CUtensorMapDataType, cuuint32_t, void*,
    const cuuint64_t*, const cuuint64_t*, const cuuint32_t*, const cuuint32_t*,
    CUtensorMapInterleave, CUtensorMapSwizzle, CUtensorMapL2promotion,
    CUtensorMapFloatOOBfill);

static void enc2d(PFN_tmencode fn, CUtensorMap* m, void* base,
                  uint64_t d0, uint64_t d1, uint64_t stride1B,
                  uint32_t b0, uint32_t b1)
{
    cuuint64_t dims[2] = {d0, d1};
    cuuint64_t str[1]  = {stride1B};
    cuuint32_t box[2]  = {b0, b1};
    cuuint32_t es[2]   = {1, 1};
    fn(m, CU_TENSOR_MAP_DATA_TYPE_FLOAT32, 2, base, dims, str, box, es,
       CU_TENSOR_MAP_INTERLEAVE_NONE, CU_TENSOR_MAP_SWIZZLE_128B,
       CU_TENSOR_MAP_L2_PROMOTION_L2_128B, CU_TENSOR_MAP_FLOAT_OOB_FILL_NONE);
}

static void enc3d(PFN_tmencode fn, CUtensorMap* m, void* base)
{
    cuuint64_t dims[3] = {Dc, Sc, (uint64_t)Bc * Hc};
    cuuint64_t str[2]  = {Dc * 4ull, (uint64_t)Sc * Dc * 4ull};
    cuuint32_t box[3]  = {32, 64, 1};
    cuuint32_t es[3]   = {1, 1, 1};
    fn(m, CU_TENSOR_MAP_DATA_TYPE_FLOAT32, 3, base, dims, str, box, es,
       CU_TENSOR_MAP_INTERLEAVE_NONE, CU_TENSOR_MAP_SWIZZLE_128B,
       CU_TENSOR_MAP_L2_PROMOTION_L2_128B, CU_TENSOR_MAP_FLOAT_OOB_FILL_NONE);
}

extern "C" void kernel_launch(void* const* d_in, const int* in_sizes, int n_in,
                              void* d_out, int out_size)
{
    const float* x  = (const float*)d_in[0];
    const float* Wq = (const float*)d_in[1];
    const float* bq = (const float*)d_in[2];
    const float* Wk = (const float*)d_in[3];
    const float* bk = (const float*)d_in[4];
    const float* Wv = (const float*)d_in[5];
    const float* bv = (const float*)d_in[6];
    const float* Wo = (const float*)d_in[7];
    const float* bo = (const float*)d_in[8];
    float* out = (float*)d_out;

    float *pQ, *pK, *pV, *pA, *pX, *pWq, *pWk, *pWv, *pWo;
    cudaGetSymbolAddress((void**)&pQ, g_Q);
    cudaGetSymbolAddress((void**)&pK, g_K);
    cudaGetSymbolAddress((void**)&pV, g_V);
    cudaGetSymbolAddress((void**)&pA, g_A);
    cudaGetSymbolAddress((void**)&pX, g_X);
    cudaGetSymbolAddress((void**)&pWq, g_Wq);
    cudaGetSymbolAddress((void**)&pWk, g_Wk);
    cudaGetSymbolAddress((void**)&pWv, g_Wv);
    cudaGetSymbolAddress((void**)&pWo, g_Wo);

    // TMA encoder via driver entry point (no -lcuda link needed)
    PFN_tmencode enc = nullptr;
    {
        void* fn = nullptr;
        cudaDriverEntryPointQueryResult qr;
        cudaGetDriverEntryPointByVersion("cuTensorMapEncodeTiled", &fn, 12000,
                                         cudaEnableDefault, &qr);
        enc = (PFN_tmencode)fn;
    }

    CUtensorMap mX, mWq, mWk, mWv, mWo, mAo, mKm, mVm;
    enc2d(enc, &mX,  pX,  Ec, Mtot, Ec * 4ull, GBK, GBM);   // A for QKV gemms
    enc2d(enc, &mWq, pWq, Ec, Ec,   Ec * 4ull, GBK, GBN);
    enc2d(enc, &mWk, pWk, Ec, Ec,   Ec * 4ull, GBK, GBN);
    enc2d(enc, &mWv, pWv, Ec, Ec,   Ec * 4ull, GBK, GBN);
    enc2d(enc, &mWo, pWo, Ec, Ec,   Ec * 4ull, GBK, GBN);
    enc2d(enc, &mAo, pA,  Ec, Mtot, Ec * 4ull, GBK, GBM);   // A for final gemm
    enc3d(enc, &mKm, pK);
    enc3d(enc, &mVm, pV);

    cudaFuncSetAttribute(gemm_tc<0>, cudaFuncAttributeMaxDynamicSharedMemorySize, GSMEM);
    cudaFuncSetAttribute(gemm_tc<1>, cudaFuncAttributeMaxDynamicSharedMemorySize, GSMEM);
    cudaFuncSetAttribute(attn_tc, cudaFuncAttributeMaxDynamicSharedMemorySize, ASMEM);

    // pre-convert x; transpose+convert weights
    const int xN4 = Mtot * Ec / 4;
    cvt_tf32<<<(xN4 + 255) / 256, 256>>>(x, pX, xN4);
    dim3 tg(Ec / 32, Ec / 32);
    cvt_tr<<<tg, 256>>>(Wq, pWq);
    cvt_tr<<<tg, 256>>>(Wk, pWk);
    cvt_tr<<<tg, 256>>>(Wv, pWv);
    cvt_tr<<<tg, 256>>>(Wo, pWo);

    dim3 gg(Ec / GBN, Mtot / GBM);   // (8, 64)
    gemm_tc<1><<<gg, 256, GSMEM>>>(mX, mWq, bq, pQ, 1);
    gemm_tc<1><<<gg, 256, GSMEM>>>(mX, mWk, bk, pK, 1);
    gemm_tc<1><<<gg, 256, GSMEM>>>(mX, mWv, bv, pV, 1);
    attn_tc<<<dim3(Sc / AQ, Hc, Bc), 256, ASMEM>>>(pQ, pK, pV, pA, mKm, mVm);
    gemm_tc<0><<<gg, 256, GSMEM>>>(mAo, mWo, bo, out, 0);
}

// round 13
// speedup vs baseline: 2.1175x; 1.0414x over previous
#include <cuda_runtime.h>
#include <cuda.h>
#include <math.h>
#include <stdint.h>

#define Bc 4
#define Sc 2048
#define Ec 1024
#define Hc 16
#define Dc 64
#define Mtot (Bc*Sc)   // 8192

// Scratch (static device globals: allocation-free). All hold tf32 bit patterns.
__device__ float g_Q[(size_t)Bc*Hc*Sc*Dc];
__device__ float g_K[(size_t)Bc*Hc*Sc*Dc];
__device__ float g_V[(size_t)Bc*Hc*Sc*Dc];
__device__ float g_A[(size_t)Bc*Sc*Ec];
__device__ float g_X[(size_t)Mtot*Ec];
__device__ float g_Wq[(size_t)Ec*Ec];   // TRANSPOSED [n][k]
__device__ float g_Wk[(size_t)Ec*Ec];   // TRANSPOSED
__device__ float g_Wv[(size_t)Ec*Ec];   // TRANSPOSED
__device__ float g_Wo[(size_t)Ec*Ec];   // TRANSPOSED

// ---- helpers --------------------------------------------------------------
__device__ __forceinline__ uint32_t f2tf(float x) {
    uint32_t u;
    asm("cvt.rna.tf32.f32 %0, %1;" : "=r"(u) : "f"(x));
    return u;
}

__device__ __forceinline__ void mma8(float* d, const uint32_t* a, const uint32_t* b) {
    asm volatile(
        "mma.sync.aligned.m16n8k8.row.col.f32.tf32.tf32.f32 "
        "{%0,%1,%2,%3}, {%4,%5,%6,%7}, {%8,%9}, {%0,%1,%2,%3};"
        : "+f"(d[0]), "+f"(d[1]), "+f"(d[2]), "+f"(d[3])
        : "r"(a[0]), "r"(a[1]), "r"(a[2]), "r"(a[3]), "r"(b[0]), "r"(b[1]));
}

__device__ __forceinline__ void cpa16(uint32_t dst, const void* src) {
    asm volatile("cp.async.cg.shared.global [%0], [%1], 16;" :: "r"(dst), "l"(src));
}
__device__ __forceinline__ void cp_commit() {
    asm volatile("cp.async.commit_group;" ::: "memory");
}
__device__ __forceinline__ void cp_wait0() {
    asm volatile("cp.async.wait_group 0;" ::: "memory");
}

__device__ __forceinline__ void mbar_init(uint32_t a, uint32_t cnt) {
    asm volatile("mbarrier.init.shared.b64 [%0], %1;" :: "r"(a), "r"(cnt) : "memory");
}
__device__ __forceinline__ void mbar_expect(uint32_t a, uint32_t bytes) {
    asm volatile("mbarrier.arrive.expect_tx.shared.b64 _, [%0], %1;"
                 :: "r"(a), "r"(bytes) : "memory");
}
__device__ __forceinline__ void mbar_wait(uint32_t a, uint32_t par) {
    asm volatile(
        "{\n\t.reg .pred P;\n\t"
        "LW%=:\n\t"
        "mbarrier.try_wait.parity.acquire.cta.shared::cta.b64 P, [%0], %1, 0x989680;\n\t"
        "@P bra LD%=;\n\t"
        "bra LW%=;\n\t"
        "LD%=:\n\t}"
        :: "r"(a), "r"(par) : "memory");
}
__device__ __forceinline__ void tma2d(uint32_t dst, const CUtensorMap* m,
                                      int x, int y, uint32_t mb) {
    asm volatile(
        "cp.async.bulk.tensor.2d.shared::cta.global.tile.mbarrier::complete_tx::bytes "
        "[%0], [%1, {%2, %3}], [%4];"
        :: "r"(dst), "l"(m), "r"(x), "r"(y), "r"(mb) : "memory");
}
__device__ __forceinline__ void tma3d(uint32_t dst, const CUtensorMap* m,
                                      int x, int y, int z, uint32_t mb) {
    asm volatile(
        "cp.async.bulk.tensor.3d.shared::cta.global.tile.mbarrier::complete_tx::bytes "
        "[%0], [%1, {%2, %3, %4}], [%5];"
        :: "r"(dst), "l"(m), "r"(x), "r"(y), "r"(z), "r"(mb) : "memory");
}

// ---- pre-convert kernels --------------------------------------------------
__global__ __launch_bounds__(256) void cvt_tf32(
    const float* __restrict__ in, float* __restrict__ out, int n4)
{
    const int i = blockIdx.x * 256 + threadIdx.x;
    if (i < n4) {
        float4 v = ((const float4*)in)[i];
        uint4 u = make_uint4(f2tf(v.x), f2tf(v.y), f2tf(v.z), f2tf(v.w));
        ((uint4*)out)[i] = u;
    }
}

// transpose + convert: out[n][k] = tf32_bits(in[k][n]); 32x32 smem tiles
__global__ __launch_bounds__(256) void cvt_tr(
    const float* __restrict__ in, float* __restrict__ out)
{
    __shared__ float t[32][33];
    const int n0 = blockIdx.x * 32, k0 = blockIdx.y * 32;
    const int tx = threadIdx.x & 31, ty = threadIdx.x >> 5;   // 32 x 8
    #pragma unroll
    for (int j = 0; j < 4; j++)
        t[ty * 4 + j][tx] =
            __uint_as_float(f2tf(in[(size_t)(k0 + ty * 4 + j) * Ec + n0 + tx]));
    __syncthreads();
    #pragma unroll
    for (int j = 0; j < 4; j++)
        out[(size_t)(n0 + ty * 4 + j) * Ec + k0 + tx] = t[tx][ty * 4 + j];
}

// ---------------- GEMM (TMA, 3-stage pipeline, optional fused z) -----------
// A smem [128 m][32 k] SW128, W smem [128 n][32 k] SW128 (W pre-transposed).
// 128x128 tile, BK=32, 256 threads, warp tile 64x32.
// blockIdx.z selects (mW, bias, C) -- fuses Q/K/V projections in one launch.
#define GBM 128
#define GBN 128
#define GBK 32
#define GSTG 32768
#define GMB  98304
#define GSMEM 98328

template<int OTF>
__global__ __launch_bounds__(256, 2) void gemm_tc(
    const __grid_constant__ CUtensorMap mA,
    const __grid_constant__ CUtensorMap mW0,
    const __grid_constant__ CUtensorMap mW1,
    const __grid_constant__ CUtensorMap mW2,
    const float* __restrict__ b0, const float* __restrict__ b1,
    const float* __restrict__ b2,
    float* __restrict__ C0, float* __restrict__ C1, float* __restrict__ C2,
    int split)
{
    extern __shared__ char smem[];
    uint32_t smb;
    asm("{ .reg .u64 t; cvta.to.shared.u64 t, %1; cvt.u32.u64 %0, t; }"
        : "=r"(smb) : "l"(smem));

    const int z = blockIdx.z;
    const CUtensorMap* mW = (z == 0) ? &mW0 : (z == 1) ? &mW1 : &mW2;
    const float* bias = (z == 0) ? b0 : (z == 1) ? b1 : b2;
    float* C = (z == 0) ? C0 : (z == 1) ? C1 : C2;

    const int tid  = threadIdx.x;
    const int lane = tid & 31, warp = tid >> 5;
    const int g = lane >> 2, tg = lane & 3;
    const int wm = warp >> 2, wn = warp & 3;
    const int bm = blockIdx.y * GBM, bn = blockIdx.x * GBN;
    const int xg = 4 * g;   // SW128 word-col XOR for rows with row&7==g

    if (tid == 0) {
        mbar_init(smb + GMB, 1); mbar_init(smb + GMB + 8, 1);
        mbar_init(smb + GMB + 16, 1);
    }
    __syncthreads();
    if (tid == 0) {
        #pragma unroll
        for (int s = 0; s < 2; s++) {
            const uint32_t mb = smb + GMB + 8 * s;
            mbar_expect(mb, GSTG);
            tma2d(smb + GSTG * s,         &mA, s * GBK, bm, mb);
            tma2d(smb + GSTG * s + 16384, mW,  s * GBK, bn, mb);
        }
    }

    float acc[4][4][4];
    #pragma unroll
    for (int mt = 0; mt < 4; mt++)
        #pragma unroll
        for (int nt = 0; nt < 4; nt++)
            #pragma unroll
            for (int i = 0; i < 4; i++) acc[mt][nt][i] = 0.f;

    const int NIT = Ec / GBK;   // 32
    for (int it = 0; it < NIT; it++) {
        const int sl = it % 3;
        if (it) __syncthreads();   // readers of slot (it+2)%3's old tile done
        if (tid == 0 && it + 2 < NIT) {
            const int s2 = (it + 2) % 3;
            const uint32_t mb = smb + GMB + 8 * s2;
            mbar_expect(mb, GSTG);
            tma2d(smb + GSTG * s2,         &mA, (it + 2) * GBK, bm, mb);
            tma2d(smb + GSTG * s2 + 16384, mW,  (it + 2) * GBK, bn, mb);
        }
        mbar_wait(smb + GMB + 8 * sl, (it / 3) & 1);

        const uint32_t* Au = (const uint32_t*)(smem + GSTG * sl);
        const uint32_t* Wu = (const uint32_t*)(smem + GSTG * sl + 16384);

        #pragma unroll
        for (int ks = 0; ks < 4; ks++) {
            const int c0 = (8 * ks + tg) ^ xg;
            const int c4 = (8 * ks + tg + 4) ^ xg;
            uint32_t af[4][4], bf[4][2];
            #pragma unroll
            for (int mt = 0; mt < 4; mt++) {
                const int r = wm * 64 + mt * 16 + g;
                af[mt][0] = Au[r * 32 + c0];
                af[mt][1] = Au[(r + 8) * 32 + c0];
                af[mt][2] = Au[r * 32 + c4];
                af[mt][3] = Au[(r + 8) * 32 + c4];
            }
            #pragma unroll
            for (int nt = 0; nt < 4; nt++) {
                const int cb = wn * 32 + nt * 8 + g;
                bf[nt][0] = Wu[cb * 32 + c0];
                bf[nt][1] = Wu[cb * 32 + c4];
            }
            #pragma unroll
            for (int mt = 0; mt < 4; mt++)
                #pragma unroll
                for (int nt = 0; nt < 4; nt++)
                    mma8(acc[mt][nt], af[mt], bf[nt]);
        }
    }

    #pragma unroll
    for (int mt = 0; mt < 4; mt++) {
        #pragma unroll
        for (int half = 0; half < 2; half++) {
            const int m = bm + wm * 64 + mt * 16 + g + half * 8;
            #pragma unroll
            for (int nt = 0; nt < 4; nt++) {
                const int n = bn + wn * 32 + nt * 8 + 2 * tg;
                float2 bb = *(const float2*)&bias[n];
                float v0 = acc[mt][nt][half * 2 + 0] + bb.x;
                float v1 = acc[mt][nt][half * 2 + 1] + bb.y;
                if (OTF) {
                    v0 = __uint_as_float(f2tf(v0));
                    v1 = __uint_as_float(f2tf(v1));
                }
                if (split) {
                    const int b = m >> 11, s = m & 2047;
                    const int h = n >> 6, d = n & 63;
                    *(float2*)&C[(((size_t)(b * Hc + h)) * Sc + s) * Dc + d] =
                        make_float2(v0, v1);
                } else {
                    *(float2*)&C[(size_t)m * Ec + n] = make_float2(v0, v1);
                }
            }
        }
    }
}

// ---------------- Flash attention (tf32 mma, P in regs, TMA K/V) -----------
// (unchanged from R12 -- proven 815-era structure)
#define AQ 128
#define QST 68
#define AQ0 0
#define AK0 34816
#define AV0 67584
#define AMB 100352
#define ASMEM 100368

__global__ __launch_bounds__(256, 2) void attn_tc(
    const float* __restrict__ Qg_, const float* __restrict__ Kg_,
    const float* __restrict__ Vg_, float* __restrict__ Ag_,
    const __grid_constant__ CUtensorMap mK,
    const __grid_constant__ CUtensorMap mV)
{
    extern __shared__ char smem[];
    uint32_t smb;
    asm("{ .reg .u64 t; cvta.to.shared.u64 t, %1; cvt.u32.u64 %0, t; }"
        : "=r"(smb) : "l"(smem));
    float* Qs = (float*)smem;   // [128][68]

    const int tid  = threadIdx.x;
    const int lane = tid & 31, warp = tid >> 5;
    const int g = lane >> 2, tg = lane & 3;
    const int q0 = warp * 16;
    const int pig = (g >> 1) + 4 * (g & 1);

    const int qt = blockIdx.x, h = blockIdx.y, b = blockIdx.z;
    const int bh = b * Hc + h;
    const float* Qg = Qg_ + ((size_t)bh * Sc + (size_t)qt * AQ) * Dc;

    if (tid == 0) { mbar_init(smb + AMB, 1); mbar_init(smb + AMB + 8, 1); }
    __syncthreads();

    const int qr = tid >> 1, qc = (tid & 1) * 32;
    {
        const uint32_t sQ = smb + AQ0 + (qr * QST + qc) * 4;
        #pragma unroll
        for (int j = 0; j < 8; j++)
            cpa16(sQ + 16 * j, Qg + (size_t)qr * Dc + qc + 4 * j);
        cp_commit();
    }
    if (tid == 0) {
        mbar_expect(smb + AMB, 32768);
        tma3d(smb + AK0,        &mK,  0, 0, bh, smb + AMB);
        tma3d(smb + AK0 + 8192, &mK, 32, 0, bh, smb + AMB);
        tma3d(smb + AV0,        &mV,  0, 0, bh, smb + AMB);
        tma3d(smb + AV0 + 8192, &mV, 32, 0, bh, smb + AMB);
    }
    cp_wait0();
    __syncthreads();   // Q visible to all

    float o[8][4];
    float mrow[2], lrow[2];
    #pragma unroll
    for (int nt = 0; nt < 8; nt++)
        #pragma unroll
        for (int i = 0; i < 4; i++) o[nt][i] = 0.f;
    mrow[0] = mrow[1] = -INFINITY;
    lrow[0] = lrow[1] = 0.f;

    const uint32_t* Qu = (const uint32_t*)Qs;
    const int NT = Sc / 64;   // 32
    for (int kt = 0; kt < NT; kt++) {
        const int p = kt & 1;
        if (kt) __syncthreads();
        if (tid == 0 && kt + 1 < NT) {
            const uint32_t mb = smb + AMB + 8 * (1 - p);
            const int kv0 = (kt + 1) * 64;
            mbar_expect(mb, 32768);
            tma3d(smb + AK0 + 16384 * (1 - p),        &mK,  0, kv0, bh, mb);
            tma3d(smb + AK0 + 16384 * (1 - p) + 8192, &mK, 32, kv0, bh, mb);
            tma3d(smb + AV0 + 16384 * (1 - p),        &mV,  0, kv0, bh, mb);
            tma3d(smb + AV0 + 16384 * (1 - p) + 8192, &mV, 32, kv0, bh, mb);
        }
        mbar_wait(smb + AMB + 8 * p, (kt >> 1) & 1);

        const uint32_t* Ku = (const uint32_t*)(smem + AK0 + 16384 * p);
        const uint32_t* Vu = (const uint32_t*)(smem + AV0 + 16384 * p);

        float s[8][4];
        #pragma unroll
        for (int nt = 0; nt < 8; nt++)
            #pragma unroll
            for (int i = 0; i < 4; i++) s[nt][i] = 0.f;

        #pragma unroll
        for (int ks = 0; ks < 8; ks++) {
            uint32_t af[4];
            af[0] = Qu[(q0 + g) * QST + ks * 8 + tg];
            af[1] = Qu[(q0 + 8 + g) * QST + ks * 8 + tg];
            af[2] = Qu[(q0 + g) * QST + ks * 8 + tg + 4];
            af[3] = Qu[(q0 + 8 + g) * QST + ks * 8 + tg + 4];
            const int blk = (ks >> 2) * 2048;
            const int d0 = 8 * (ks & 3) + tg;
            const int xp = 4 * pig;
            #pragma unroll
            for (int nt = 0; nt < 8; nt++) {
                const int row = (8 * nt + pig) * 32;
                uint32_t bf[2];
                bf[0] = Ku[blk + row + (d0 ^ xp)];
                bf[1] = Ku[blk + row + ((d0 + 4) ^ xp)];
                mma8(s[nt], af, bf);
            }
        }

        #pragma unroll
        for (int half = 0; half < 2; half++) {
            float tmax = -INFINITY;
            #pragma unroll
            for (int nt = 0; nt < 8; nt++) {
                s[nt][half * 2 + 0] *= 0.125f;
                s[nt][half * 2 + 1] *= 0.125f;
                tmax = fmaxf(tmax, s[nt][half * 2 + 0]);
                tmax = fmaxf(tmax, s[nt][half * 2 + 1]);
            }
            tmax = fmaxf(tmax, __shfl_xor_sync(0xffffffffu, tmax, 1));
            tmax = fmaxf(tmax, __shfl_xor_sync(0xffffffffu, tmax, 2));
            const float mn   = fmaxf(mrow[half], tmax);
            const float corr = __expf(mrow[half] - mn);
            float rs = 0.f;
            #pragma unroll
            for (int nt = 0; nt < 8; nt++) {
                float p0 = __expf(s[nt][half * 2 + 0] - mn);
                float p1 = __expf(s[nt][half * 2 + 1] - mn);
                s[nt][half * 2 + 0] = p0;
                s[nt][half * 2 + 1] = p1;
                rs += p0 + p1;
                o[nt][half * 2 + 0] *= corr;
                o[nt][half * 2 + 1] *= corr;
            }
            rs += __shfl_xor_sync(0xffffffffu, rs, 1);
            rs += __shfl_xor_sync(0xffffffffu, rs, 2);
            lrow[half] = lrow[half] * corr + rs;
            mrow[half] = mn;
        }

        #pragma unroll
        for (int ks = 0; ks < 8; ks++) {
            uint32_t af[4];
            af[0] = f2tf(s[ks][0]);
            af[1] = f2tf(s[ks][2]);
            af[2] = f2tf(s[ks][1]);
            af[3] = f2tf(s[ks][3]);
            const int r0 = (8 * ks + tg) * 32;
            const int r4 = (8 * ks + tg + 4) * 32;
            const int x0 = 4 * tg;
            const int x4 = 4 * tg + 16;
            #pragma unroll
            for (int nt = 0; nt < 8; nt++) {
                const int blk = (nt >> 2) * 2048;
                const int dc = (8 * nt + g) & 31;
                uint32_t bf[2];
                bf[0] = Vu[blk + r0 + (dc ^ x0)];
                bf[1] = Vu[blk + r4 + (dc ^ x4)];
                mma8(o[nt], af, bf);
            }
        }
    }

    #pragma unroll
    for (int half = 0; half < 2; half++) {
        const float inv = 1.f / lrow[half];
        const int q = qt * AQ + q0 + g + half * 8;
        #pragma unroll
        for (int nt = 0; nt < 8; nt++) {
            const int d = nt * 8 + 2 * tg;
            float2 w = make_float2(
                __uint_as_float(f2tf(o[nt][half * 2 + 0] * inv)),
                __uint_as_float(f2tf(o[nt][half * 2 + 1] * inv)));
            *(float2*)&Ag_[((size_t)b * Sc + q) * Ec + h * Dc + d] = w;
        }
    }
}

// ---------------------------------------------------------------------------
typedef CUresult (*PFN_tmencode)(
    CUtensorMap*, CUtensorMapDataType, cuuint32_t, void*,
    const cuuint64_t*, const cuuint64_t*, const cuuint32_t*, const cuuint32_t*,
    CUtensorMapInterleave, CUtensorMapSwizzle, CUtensorMapL2promotion,
    CUtensorMapFloatOOBfill);

static void enc2d(PFN_tmencode fn, CUtensorMap* m, void* base,
                  uint64_t d0, uint64_t d1, uint64_t stride1B,
                  uint32_t b0, uint32_t b1)
{
    cuuint64_t dims[2] = {d0, d1};
    cuuint64_t str[1]  = {stride1B};
    cuuint32_t box[2]  = {b0, b1};
    cuuint32_t es[2]   = {1, 1};
    fn(m, CU_TENSOR_MAP_DATA_TYPE_FLOAT32, 2, base, dims, str, box, es,
       CU_TENSOR_MAP_INTERLEAVE_NONE, CU_TENSOR_MAP_SWIZZLE_128B,
       CU_TENSOR_MAP_L2_PROMOTION_L2_128B, CU_TENSOR_MAP_FLOAT_OOB_FILL_NONE);
}

static void enc3d(PFN_tmencode fn, CUtensorMap* m, void* base)
{
    cuuint64_t dims[3] = {Dc, Sc, (uint64_t)Bc * Hc};
    cuuint64_t str[2]  = {Dc * 4ull, (uint64_t)Sc * Dc * 4ull};
    cuuint32_t box[3]  = {32, 64, 1};
    cuuint32_t es[3]   = {1, 1, 1};
    fn(m, CU_TENSOR_MAP_DATA_TYPE_FLOAT32, 3, base, dims, str, box, es,
       CU_TENSOR_MAP_INTERLEAVE_NONE, CU_TENSOR_MAP_SWIZZLE_128B,
       CU_TENSOR_MAP_L2_PROMOTION_L2_128B, CU_TENSOR_MAP_FLOAT_OOB_FILL_NONE);
}

extern "C" void kernel_launch(void* const* d_in, const int* in_sizes, int n_in,
                              void* d_out, int out_size)
{
    const float* x  = (const float*)d_in[0];
    const float* Wq = (const float*)d_in[1];
    const float* bq = (const float*)d_in[2];
    const float* Wk = (const float*)d_in[3];
    const float* bk = (const float*)d_in[4];
    const float* Wv = (const float*)d_in[5];
    const float* bv = (const float*)d_in[6];
    const float* Wo = (const float*)d_in[7];
    const float* bo = (const float*)d_in[8];
    float* out = (float*)d_out;

    float *pQ, *pK, *pV, *pA, *pX, *pWq, *pWk, *pWv, *pWo;
    cudaGetSymbolAddress((void**)&pQ, g_Q);
    cudaGetSymbolAddress((void**)&pK, g_K);
    cudaGetSymbolAddress((void**)&pV, g_V);
    cudaGetSymbolAddress((void**)&pA, g_A);
    cudaGetSymbolAddress((void**)&pX, g_X);
    cudaGetSymbolAddress((void**)&pWq, g_Wq);
    cudaGetSymbolAddress((void**)&pWk, g_Wk);
    cudaGetSymbolAddress((void**)&pWv, g_Wv);
    cudaGetSymbolAddress((void**)&pWo, g_Wo);

    PFN_tmencode enc = nullptr;
    {
        void* fn = nullptr;
        cudaDriverEntryPointQueryResult qr;
        cudaGetDriverEntryPointByVersion("cuTensorMapEncodeTiled", &fn, 12000,
                                         cudaEnableDefault, &qr);
        enc = (PFN_tmencode)fn;
    }

    CUtensorMap mX, mWq, mWk, mWv, mWo, mAo, mKm, mVm;
    enc2d(enc, &mX,  pX,  Ec, Mtot, Ec * 4ull, GBK, GBM);
    enc2d(enc, &mWq, pWq, Ec, Ec,   Ec * 4ull, GBK, GBN);
    enc2d(enc, &mWk, pWk, Ec, Ec,   Ec * 4ull, GBK, GBN);
    enc2d(enc, &mWv, pWv, Ec, Ec,   Ec * 4ull, GBK, GBN);
    enc2d(enc, &mWo, pWo, Ec, Ec,   Ec * 4ull, GBK, GBN);
    enc2d(enc, &mAo, pA,  Ec, Mtot, Ec * 4ull, GBK, GBM);
    enc3d(enc, &mKm, pK);
    enc3d(enc, &mVm, pV);

    cudaFuncSetAttribute(gemm_tc<0>, cudaFuncAttributeMaxDynamicSharedMemorySize, GSMEM);
    cudaFuncSetAttribute(gemm_tc<1>, cudaFuncAttributeMaxDynamicSharedMemorySize, GSMEM);
    cudaFuncSetAttribute(attn_tc, cudaFuncAttributeMaxDynamicSharedMemorySize, ASMEM);

    const int xN4 = Mtot * Ec / 4;
    cvt_tf32<<<(xN4 + 255) / 256, 256>>>(x, pX, xN4);
    dim3 tgv(Ec / 32, Ec / 32);
    cvt_tr<<<tgv, 256>>>(Wq, pWq);
    cvt_tr<<<tgv, 256>>>(Wk, pWk);
    cvt_tr<<<tgv, 256>>>(Wv, pWv);
    cvt_tr<<<tgv, 256>>>(Wo, pWo);

    // fused Q/K/V projection: z selects weight/bias/out
    gemm_tc<1><<<dim3(Ec / GBN, Mtot / GBM, 3), 256, GSMEM>>>(
        mX, mWq, mWk, mWv, bq, bk, bv, pQ, pK, pV, 1);
    attn_tc<<<dim3(Sc / AQ, Hc, Bc), 256, ASMEM>>>(pQ, pK, pV, pA, mKm, mVm);
    gemm_tc<0><<<dim3(Ec / GBN, Mtot / GBM, 1), 256, GSMEM>>>(
        mAo, mWo, mWo, mWo, bo, bo, bo, out, out, out, 0);
}

// round 14
// speedup vs baseline: 2.6246x; 1.2395x over previous
#include <cuda_runtime.h>
#include <cuda.h>
#include <cuda_fp16.h>
#include <math.h>
#include <stdint.h>

#define Bc 4
#define Sc 2048
#define Ec 1024
#define Hc 16
#define Dc 64
#define Mtot (Bc*Sc)   // 8192

// Scratch (static device globals: allocation-free).
__device__ float  g_Q[(size_t)Bc*Hc*Sc*Dc];   // tf32 bits (attn input)
__device__ float  g_K[(size_t)Bc*Hc*Sc*Dc];   // tf32 bits
__device__ float  g_V[(size_t)Bc*Hc*Sc*Dc];   // tf32 bits
__device__ __half g_Ah[(size_t)Bc*Sc*Ec];     // attn output, fp16
__device__ __half g_Xh[(size_t)Mtot*Ec];      // x, fp16
__device__ __half g_Wq[(size_t)Ec*Ec];        // TRANSPOSED [n][k], fp16
__device__ __half g_Wk[(size_t)Ec*Ec];
__device__ __half g_Wv[(size_t)Ec*Ec];
__device__ __half g_Wo[(size_t)Ec*Ec];

// ---- helpers --------------------------------------------------------------
__device__ __forceinline__ uint32_t f2tf(float x) {
    uint32_t u;
    asm("cvt.rna.tf32.f32 %0, %1;" : "=r"(u) : "f"(x));
    return u;
}

// tf32 m16n8k8 (attention)
__device__ __forceinline__ void mma8(float* d, const uint32_t* a, const uint32_t* b) {
    asm volatile(
        "mma.sync.aligned.m16n8k8.row.col.f32.tf32.tf32.f32 "
        "{%0,%1,%2,%3}, {%4,%5,%6,%7}, {%8,%9}, {%0,%1,%2,%3};"
        : "+f"(d[0]), "+f"(d[1]), "+f"(d[2]), "+f"(d[3])
        : "r"(a[0]), "r"(a[1]), "r"(a[2]), "r"(a[3]), "r"(b[0]), "r"(b[1]));
}

// fp16 m16n8k16 (GEMMs)
__device__ __forceinline__ void mma16(float* d, const uint32_t* a, const uint32_t* b) {
    asm volatile(
        "mma.sync.aligned.m16n8k16.row.col.f32.f16.f16.f32 "
        "{%0,%1,%2,%3}, {%4,%5,%6,%7}, {%8,%9}, {%0,%1,%2,%3};"
        : "+f"(d[0]), "+f"(d[1]), "+f"(d[2]), "+f"(d[3])
        : "r"(a[0]), "r"(a[1]), "r"(a[2]), "r"(a[3]), "r"(b[0]), "r"(b[1]));
}

__device__ __forceinline__ void cpa16(uint32_t dst, const void* src) {
    asm volatile("cp.async.cg.shared.global [%0], [%1], 16;" :: "r"(dst), "l"(src));
}
__device__ __forceinline__ void cp_commit() {
    asm volatile("cp.async.commit_group;" ::: "memory");
}
__device__ __forceinline__ void cp_wait0() {
    asm volatile("cp.async.wait_group 0;" ::: "memory");
}

__device__ __forceinline__ void mbar_init(uint32_t a, uint32_t cnt) {
    asm volatile("mbarrier.init.shared.b64 [%0], %1;" :: "r"(a), "r"(cnt) : "memory");
}
__device__ __forceinline__ void mbar_expect(uint32_t a, uint32_t bytes) {
    asm volatile("mbarrier.arrive.expect_tx.shared.b64 _, [%0], %1;"
                 :: "r"(a), "r"(bytes) : "memory");
}
__device__ __forceinline__ void mbar_wait(uint32_t a, uint32_t par) {
    asm volatile(
        "{\n\t.reg .pred P;\n\t"
        "LW%=:\n\t"
        "mbarrier.try_wait.parity.acquire.cta.shared::cta.b64 P, [%0], %1, 0x989680;\n\t"
        "@P bra LD%=;\n\t"
        "bra LW%=;\n\t"
        "LD%=:\n\t}"
        :: "r"(a), "r"(par) : "memory");
}
__device__ __forceinline__ void tma2d(uint32_t dst, const CUtensorMap* m,
                                      int x, int y, uint32_t mb) {
    asm volatile(
        "cp.async.bulk.tensor.2d.shared::cta.global.tile.mbarrier::complete_tx::bytes "
        "[%0], [%1, {%2, %3}], [%4];"
        :: "r"(dst), "l"(m), "r"(x), "r"(y), "r"(mb) : "memory");
}
__device__ __forceinline__ void tma3d(uint32_t dst, const CUtensorMap* m,
                                      int x, int y, int z, uint32_t mb) {
    asm volatile(
        "cp.async.bulk.tensor.3d.shared::cta.global.tile.mbarrier::complete_tx::bytes "
        "[%0], [%1, {%2, %3, %4}], [%5];"
        :: "r"(dst), "l"(m), "r"(x), "r"(y), "r"(z), "r"(mb) : "memory");
}

// ---- pre-convert kernels --------------------------------------------------
__global__ __launch_bounds__(256) void cvt_f16(
    const float* __restrict__ in, __half* __restrict__ out, int n4)
{
    const int i = blockIdx.x * 256 + threadIdx.x;
    if (i < n4) {
        float4 v = ((const float4*)in)[i];
        __half2* o2 = (__half2*)out + 2 * i;
        o2[0] = __floats2half2_rn(v.x, v.y);
        o2[1] = __floats2half2_rn(v.z, v.w);
    }
}

// transpose + convert to fp16: out[n][k] = f16(in[k][n]); 32x32 smem tiles
__global__ __launch_bounds__(256) void cvt_tr16(
    const float* __restrict__ in, __half* __restrict__ out)
{
    __shared__ float t[32][33];
    const int n0 = blockIdx.x * 32, k0 = blockIdx.y * 32;
    const int tx = threadIdx.x & 31, ty = threadIdx.x >> 5;   // 32 x 8
    #pragma unroll
    for (int j = 0; j < 4; j++)
        t[ty * 4 + j][tx] = in[(size_t)(k0 + ty * 4 + j) * Ec + n0 + tx];
    __syncthreads();
    #pragma unroll
    for (int j = 0; j < 4; j++)
        out[(size_t)(n0 + ty * 4 + j) * Ec + k0 + tx] =
            __float2half_rn(t[tx][ty * 4 + j]);
}

// ---------------- GEMM fp16 (TMA, 3-stage, fused z) ------------------------
// A smem [128 m][64 k] halves SW128 (32 words/row), W smem [128 n][64 k].
// 128x128 tile, BK=64, 256 threads, warp tile 64x32, m16n8k16.
// Word-level indexing identical to the proven tf32 version.
#define GBM 128
#define GBN 128
#define GBK 64
#define GSTG 32768
#define GMB  98304
#define GSMEM 98328

template<int OTF>
__global__ __launch_bounds__(256, 2) void gemm_tc(
    const __grid_constant__ CUtensorMap mA,
    const __grid_constant__ CUtensorMap mW0,
    const __grid_constant__ CUtensorMap mW1,
    const __grid_constant__ CUtensorMap mW2,
    const float* __restrict__ b0, const float* __restrict__ b1,
    const float* __restrict__ b2,
    float* __restrict__ C0, float* __restrict__ C1, float* __restrict__ C2,
    int split)
{
    extern __shared__ char smem[];
    uint32_t smb;
    asm("{ .reg .u64 t; cvta.to.shared.u64 t, %1; cvt.u32.u64 %0, t; }"
        : "=r"(smb) : "l"(smem));

    const int z = blockIdx.z;
    const CUtensorMap* mW = (z == 0) ? &mW0 : (z == 1) ? &mW1 : &mW2;
    const float* bias = (z == 0) ? b0 : (z == 1) ? b1 : b2;
    float* C = (z == 0) ? C0 : (z == 1) ? C1 : C2;

    const int tid  = threadIdx.x;
    const int lane = tid & 31, warp = tid >> 5;
    const int g = lane >> 2, tg = lane & 3;
    const int wm = warp >> 2, wn = warp & 3;
    const int bm = blockIdx.y * GBM, bn = blockIdx.x * GBN;
    const int xg = 4 * g;   // SW128 word-col XOR for rows with row&7==g

    if (tid == 0) {
        mbar_init(smb + GMB, 1); mbar_init(smb + GMB + 8, 1);
        mbar_init(smb + GMB + 16, 1);
    }
    __syncthreads();
    if (tid == 0) {
        #pragma unroll
        for (int s = 0; s < 2; s++) {
            const uint32_t mb = smb + GMB + 8 * s;
            mbar_expect(mb, GSTG);
            tma2d(smb + GSTG * s,         &mA, s * GBK, bm, mb);
            tma2d(smb + GSTG * s + 16384, mW,  s * GBK, bn, mb);
        }
    }

    float acc[4][4][4];
    #pragma unroll
    for (int mt = 0; mt < 4; mt++)
        #pragma unroll
        for (int nt = 0; nt < 4; nt++)
            #pragma unroll
            for (int i = 0; i < 4; i++) acc[mt][nt][i] = 0.f;

    const int NIT = Ec / GBK;   // 16
    for (int it = 0; it < NIT; it++) {
        const int sl = it % 3;
        if (it) __syncthreads();
        if (tid == 0 && it + 2 < NIT) {
            const int s2 = (it + 2) % 3;
            const uint32_t mb = smb + GMB + 8 * s2;
            mbar_expect(mb, GSTG);
            tma2d(smb + GSTG * s2,         &mA, (it + 2) * GBK, bm, mb);
            tma2d(smb + GSTG * s2 + 16384, mW,  (it + 2) * GBK, bn, mb);
        }
        mbar_wait(smb + GMB + 8 * sl, (it / 3) & 1);

        const uint32_t* Au = (const uint32_t*)(smem + GSTG * sl);
        const uint32_t* Wu = (const uint32_t*)(smem + GSTG * sl + 16384);

        #pragma unroll
        for (int ks = 0; ks < 4; ks++) {   // 4 k16-steps cover 64 halves
            const int c0 = (8 * ks + tg) ^ xg;
            const int c4 = (8 * ks + tg + 4) ^ xg;
            uint32_t af[4][4], bf[4][2];
            #pragma unroll
            for (int mt = 0; mt < 4; mt++) {
                const int r = wm * 64 + mt * 16 + g;
                af[mt][0] = Au[r * 32 + c0];
                af[mt][1] = Au[(r + 8) * 32 + c0];
                af[mt][2] = Au[r * 32 + c4];
                af[mt][3] = Au[(r + 8) * 32 + c4];
            }
            #pragma unroll
            for (int nt = 0; nt < 4; nt++) {
                const int cb = wn * 32 + nt * 8 + g;
                bf[nt][0] = Wu[cb * 32 + c0];
                bf[nt][1] = Wu[cb * 32 + c4];
            }
            #pragma unroll
            for (int mt = 0; mt < 4; mt++)
                #pragma unroll
                for (int nt = 0; nt < 4; nt++)
                    mma16(acc[mt][nt], af[mt], bf[nt]);
        }
    }

    #pragma unroll
    for (int mt = 0; mt < 4; mt++) {
        #pragma unroll
        for (int half = 0; half < 2; half++) {
            const int m = bm + wm * 64 + mt * 16 + g + half * 8;
            #pragma unroll
            for (int nt = 0; nt < 4; nt++) {
                const int n = bn + wn * 32 + nt * 8 + 2 * tg;
                float2 bb = *(const float2*)&bias[n];
                float v0 = acc[mt][nt][half * 2 + 0] + bb.x;
                float v1 = acc[mt][nt][half * 2 + 1] + bb.y;
                if (OTF) {   // tf32 bits for the attention kernel
                    v0 = __uint_as_float(f2tf(v0));
                    v1 = __uint_as_float(f2tf(v1));
                }
                if (split) {
                    const int b = m >> 11, s = m & 2047;
                    const int h = n >> 6, d = n & 63;
                    *(float2*)&C[(((size_t)(b * Hc + h)) * Sc + s) * Dc + d] =
                        make_float2(v0, v1);
                } else {
                    *(float2*)&C[(size_t)m * Ec + n] = make_float2(v0, v1);
                }
            }
        }
    }
}

// ---------------- Flash attention (tf32 mma, P in regs, TMA K/V) -----------
// Unchanged compute from R12/R13; epilogue now writes g_Ah as fp16.
#define AQ 128
#define QST 68
#define AQ0 0
#define AK0 34816
#define AV0 67584
#define AMB 100352
#define ASMEM 100368

__global__ __launch_bounds__(256, 2) void attn_tc(
    const float* __restrict__ Qg_, const float* __restrict__ Kg_,
    const float* __restrict__ Vg_, __half* __restrict__ Ag_,
    const __grid_constant__ CUtensorMap mK,
    const __grid_constant__ CUtensorMap mV)
{
    extern __shared__ char smem[];
    uint32_t smb;
    asm("{ .reg .u64 t; cvta.to.shared.u64 t, %1; cvt.u32.u64 %0, t; }"
        : "=r"(smb) : "l"(smem));
    float* Qs = (float*)smem;   // [128][68]

    const int tid  = threadIdx.x;
    const int lane = tid & 31, warp = tid >> 5;
    const int g = lane >> 2, tg = lane & 3;
    const int q0 = warp * 16;
    const int pig = (g >> 1) + 4 * (g & 1);

    const int qt = blockIdx.x, h = blockIdx.y, b = blockIdx.z;
    const int bh = b * Hc + h;
    const float* Qg = Qg_ + ((size_t)bh * Sc + (size_t)qt * AQ) * Dc;

    if (tid == 0) { mbar_init(smb + AMB, 1); mbar_init(smb + AMB + 8, 1); }
    __syncthreads();

    const int qr = tid >> 1, qc = (tid & 1) * 32;
    {
        const uint32_t sQ = smb + AQ0 + (qr * QST + qc) * 4;
        #pragma unroll
        for (int j = 0; j < 8; j++)
            cpa16(sQ + 16 * j, Qg + (size_t)qr * Dc + qc + 4 * j);
        cp_commit();
    }
    if (tid == 0) {
        mbar_expect(smb + AMB, 32768);
        tma3d(smb + AK0,        &mK,  0, 0, bh, smb + AMB);
        tma3d(smb + AK0 + 8192, &mK, 32, 0, bh, smb + AMB);
        tma3d(smb + AV0,        &mV,  0, 0, bh, smb + AMB);
        tma3d(smb + AV0 + 8192, &mV, 32, 0, bh, smb + AMB);
    }
    cp_wait0();
    __syncthreads();   // Q visible to all

    float o[8][4];
    float mrow[2], lrow[2];
    #pragma unroll
    for (int nt = 0; nt < 8; nt++)
        #pragma unroll
        for (int i = 0; i < 4; i++) o[nt][i] = 0.f;
    mrow[0] = mrow[1] = -INFINITY;
    lrow[0] = lrow[1] = 0.f;

    const uint32_t* Qu = (const uint32_t*)Qs;
    const int NT = Sc / 64;   // 32
    for (int kt = 0; kt < NT; kt++) {
        const int p = kt & 1;
        if (kt) __syncthreads();
        if (tid == 0 && kt + 1 < NT) {
            const uint32_t mb = smb + AMB + 8 * (1 - p);
            const int kv0 = (kt + 1) * 64;
            mbar_expect(mb, 32768);
            tma3d(smb + AK0 + 16384 * (1 - p),        &mK,  0, kv0, bh, mb);
            tma3d(smb + AK0 + 16384 * (1 - p) + 8192, &mK, 32, kv0, bh, mb);
            tma3d(smb + AV0 + 16384 * (1 - p),        &mV,  0, kv0, bh, mb);
            tma3d(smb + AV0 + 16384 * (1 - p) + 8192, &mV, 32, kv0, bh, mb);
        }
        mbar_wait(smb + AMB + 8 * p, (kt >> 1) & 1);

        const uint32_t* Ku = (const uint32_t*)(smem + AK0 + 16384 * p);
        const uint32_t* Vu = (const uint32_t*)(smem + AV0 + 16384 * p);

        float s[8][4];
        #pragma unroll
        for (int nt = 0; nt < 8; nt++)
            #pragma unroll
            for (int i = 0; i < 4; i++) s[nt][i] = 0.f;

        #pragma unroll
        for (int ks = 0; ks < 8; ks++) {
            uint32_t af[4];
            af[0] = Qu[(q0 + g) * QST + ks * 8 + tg];
            af[1] = Qu[(q0 + 8 + g) * QST + ks * 8 + tg];
            af[2] = Qu[(q0 + g) * QST + ks * 8 + tg + 4];
            af[3] = Qu[(q0 + 8 + g) * QST + ks * 8 + tg + 4];
            const int blk = (ks >> 2) * 2048;
            const int d0 = 8 * (ks & 3) + tg;
            const int xp = 4 * pig;
            #pragma unroll
            for (int nt = 0; nt < 8; nt++) {
                const int row = (8 * nt + pig) * 32;
                uint32_t bf[2];
                bf[0] = Ku[blk + row + (d0 ^ xp)];
                bf[1] = Ku[blk + row + ((d0 + 4) ^ xp)];
                mma8(s[nt], af, bf);
            }
        }

        #pragma unroll
        for (int half = 0; half < 2; half++) {
            float tmax = -INFINITY;
            #pragma unroll
            for (int nt = 0; nt < 8; nt++) {
                s[nt][half * 2 + 0] *= 0.125f;
                s[nt][half * 2 + 1] *= 0.125f;
                tmax = fmaxf(tmax, s[nt][half * 2 + 0]);
                tmax = fmaxf(tmax, s[nt][half * 2 + 1]);
            }
            tmax = fmaxf(tmax, __shfl_xor_sync(0xffffffffu, tmax, 1));
            tmax = fmaxf(tmax, __shfl_xor_sync(0xffffffffu, tmax, 2));
            const float mn   = fmaxf(mrow[half], tmax);
            const float corr = __expf(mrow[half] - mn);
            float rs = 0.f;
            #pragma unroll
            for (int nt = 0; nt < 8; nt++) {
                float p0 = __expf(s[nt][half * 2 + 0] - mn);
                float p1 = __expf(s[nt][half * 2 + 1] - mn);
                s[nt][half * 2 + 0] = p0;
                s[nt][half * 2 + 1] = p1;
                rs += p0 + p1;
                o[nt][half * 2 + 0] *= corr;
                o[nt][half * 2 + 1] *= corr;
            }
            rs += __shfl_xor_sync(0xffffffffu, rs, 1);
            rs += __shfl_xor_sync(0xffffffffu, rs, 2);
            lrow[half] = lrow[half] * corr + rs;
            mrow[half] = mn;
        }

        #pragma unroll
        for (int ks = 0; ks < 8; ks++) {
            uint32_t af[4];
            af[0] = f2tf(s[ks][0]);
            af[1] = f2tf(s[ks][2]);
            af[2] = f2tf(s[ks][1]);
            af[3] = f2tf(s[ks][3]);
            const int r0 = (8 * ks + tg) * 32;
            const int r4 = (8 * ks + tg + 4) * 32;
            const int x0 = 4 * tg;
            const int x4 = 4 * tg + 16;
            #pragma unroll
            for (int nt = 0; nt < 8; nt++) {
                const int blk = (nt >> 2) * 2048;
                const int dc = (8 * nt + g) & 31;
                uint32_t bf[2];
                bf[0] = Vu[blk + r0 + (dc ^ x0)];
                bf[1] = Vu[blk + r4 + (dc ^ x4)];
                mma8(o[nt], af, bf);
            }
        }
    }

    // Epilogue: normalize, write concat [B,S,E] as fp16 (for fp16 Wo GEMM)
    #pragma unroll
    for (int half = 0; half < 2; half++) {
        const float inv = 1.f / lrow[half];
        const int q = qt * AQ + q0 + g + half * 8;
        #pragma unroll
        for (int nt = 0; nt < 8; nt++) {
            const int d = nt * 8 + 2 * tg;
            __half2* dst = (__half2*)&Ag_[((size_t)b * Sc + q) * Ec + h * Dc + d];
            *dst = __floats2half2_rn(o[nt][half * 2 + 0] * inv,
                                     o[nt][half * 2 + 1] * inv);
        }
    }
}

// ---------------------------------------------------------------------------
typedef CUresult (*PFN_tmencode)(
    CUtensorMap*, CUtensorMapDataType, cuuint32_t, void*,
    const cuuint64_t*, const cuuint64_t*, const cuuint32_t*, const cuuint32_t*,
    CUtensorMapInterleave, CUtensorMapSwizzle, CUtensorMapL2promotion,
    CUtensorMapFloatOOBfill);

static void enc2d(PFN_tmencode fn, CUtensorMap* m, void* base,
                  CUtensorMapDataType dt,
                  uint64_t d0, uint64_t d1, uint64_t stride1B,
                  uint32_t b0, uint32_t b1)
{
    cuuint64_t dims[2] = {d0, d1};
    cuuint64_t str[1]  = {stride1B};
    cuuint32_t box[2]  = {b0, b1};
    cuuint32_t es[2]   = {1, 1};
    fn(m, dt, 2, base, dims, str, box, es,
       CU_TENSOR_MAP_INTERLEAVE_NONE, CU_TENSOR_MAP_SWIZZLE_128B,
       CU_TENSOR_MAP_L2_PROMOTION_L2_128B, CU_TENSOR_MAP_FLOAT_OOB_FILL_NONE);
}

static void enc3d(PFN_tmencode fn, CUtensorMap* m, void* base)
{
    cuuint64_t dims[3] = {Dc, Sc, (uint64_t)Bc * Hc};
    cuuint64_t str[2]  = {Dc * 4ull, (uint64_t)Sc * Dc * 4ull};
    cuuint32_t box[3]  = {32, 64, 1};
    cuuint32_t es[3]   = {1, 1, 1};
    fn(m, CU_TENSOR_MAP_DATA_TYPE_FLOAT32, 3, base, dims, str, box, es,
       CU_TENSOR_MAP_INTERLEAVE_NONE, CU_TENSOR_MAP_SWIZZLE_128B,
       CU_TENSOR_MAP_L2_PROMOTION_L2_128B, CU_TENSOR_MAP_FLOAT_OOB_FILL_NONE);
}

extern "C" void kernel_launch(void* const* d_in, const int* in_sizes, int n_in,
                              void* d_out, int out_size)
{
    const float* x  = (const float*)d_in[0];
    const float* Wq = (const float*)d_in[1];
    const float* bq = (const float*)d_in[2];
    const float* Wk = (const float*)d_in[3];
    const float* bk = (const float*)d_in[4];
    const float* Wv = (const float*)d_in[5];
    const float* bv = (const float*)d_in[6];
    const float* Wo = (const float*)d_in[7];
    const float* bo = (const float*)d_in[8];
    float* out = (float*)d_out;

    float *pQ, *pK, *pV;
    __half *pAh, *pXh, *pWq, *pWk, *pWv, *pWo;
    cudaGetSymbolAddress((void**)&pQ, g_Q);
    cudaGetSymbolAddress((void**)&pK, g_K);
    cudaGetSymbolAddress((void**)&pV, g_V);
    cudaGetSymbolAddress((void**)&pAh, g_Ah);
    cudaGetSymbolAddress((void**)&pXh, g_Xh);
    cudaGetSymbolAddress((void**)&pWq, g_Wq);
    cudaGetSymbolAddress((void**)&pWk, g_Wk);
    cudaGetSymbolAddress((void**)&pWv, g_Wv);
    cudaGetSymbolAddress((void**)&pWo, g_Wo);

    PFN_tmencode enc = nullptr;
    {
        void* fn = nullptr;
        cudaDriverEntryPointQueryResult qr;
        cudaGetDriverEntryPointByVersion("cuTensorMapEncodeTiled", &fn, 12000,
                                         cudaEnableDefault, &qr);
        enc = (PFN_tmencode)fn;
    }

    const CUtensorMapDataType F16 = CU_TENSOR_MAP_DATA_TYPE_FLOAT16;
    CUtensorMap mX, mWq, mWk, mWv, mWo, mAo, mKm, mVm;
    enc2d(enc, &mX,  pXh, F16, Ec, Mtot, Ec * 2ull, GBK, GBM);
    enc2d(enc, &mWq, pWq, F16, Ec, Ec,   Ec * 2ull, GBK, GBN);
    enc2d(enc, &mWk, pWk, F16, Ec, Ec,   Ec * 2ull, GBK, GBN);
    enc2d(enc, &mWv, pWv, F16, Ec, Ec,   Ec * 2ull, GBK, GBN);
    enc2d(enc, &mWo, pWo, F16, Ec, Ec,   Ec * 2ull, GBK, GBN);
    enc2d(enc, &mAo, pAh, F16, Ec, Mtot, Ec * 2ull, GBK, GBM);
    enc3d(enc, &mKm, pK);
    enc3d(enc, &mVm, pV);

    cudaFuncSetAttribute(gemm_tc<0>, cudaFuncAttributeMaxDynamicSharedMemorySize, GSMEM);
    cudaFuncSetAttribute(gemm_tc<1>, cudaFuncAttributeMaxDynamicSharedMemorySize, GSMEM);
    cudaFuncSetAttribute(attn_tc, cudaFuncAttributeMaxDynamicSharedMemorySize, ASMEM);

    const int xN4 = Mtot * Ec / 4;
    cvt_f16<<<(xN4 + 255) / 256, 256>>>(x, pXh, xN4);
    dim3 tgv(Ec / 32, Ec / 32);
    cvt_tr16<<<tgv, 256>>>(Wq, pWq);
    cvt_tr16<<<tgv, 256>>>(Wk, pWk);
    cvt_tr16<<<tgv, 256>>>(Wv, pWv);
    cvt_tr16<<<tgv, 256>>>(Wo, pWo);

    // fused Q/K/V projection (fp16 mma): z selects weight/bias/out
    gemm_tc<1><<<dim3(Ec / GBN, Mtot / GBM, 3), 256, GSMEM>>>(
        mX, mWq, mWk, mWv, bq, bk, bv, pQ, pK, pV, 1);
    attn_tc<<<dim3(Sc / AQ, Hc, Bc), 256, ASMEM>>>(pQ, pK, pV, pAh, mKm, mVm);
    gemm_tc<0><<<dim3(Ec / GBN, Mtot / GBM, 1), 256, GSMEM>>>(
        mAo, mWo, mWo, mWo, bo, bo, bo, out, out, out, 0);
}

// round 15
// speedup vs baseline: 3.7810x; 1.4406x over previous
#include <cuda_runtime.h>
#include <cuda.h>
#include <cuda_fp16.h>
#include <math.h>
#include <stdint.h>

#define Bc 4
#define Sc 2048
#define Ec 1024
#define Hc 16
#define Dc 64
#define Mtot (Bc*Sc)   // 8192
#define BH  (Bc*Hc)    // 64

// Scratch (static device globals: allocation-free).
__device__ __half g_Qh[(size_t)BH*Sc*Dc];     // [bh][s][d] fp16
__device__ __half g_Kh[(size_t)BH*Sc*Dc];     // [bh][s][d] fp16
__device__ __half g_Vt[(size_t)BH*Dc*Sc];     // [bh][d][s] fp16 (TRANSPOSED)
__device__ __half g_Ah[(size_t)Bc*Sc*Ec];     // attn output, fp16
__device__ __half g_Xh[(size_t)Mtot*Ec];      // x, fp16
__device__ __half g_Wq[(size_t)Ec*Ec];        // TRANSPOSED [n][k], fp16
__device__ __half g_Wk[(size_t)Ec*Ec];
__device__ __half g_Wv[(size_t)Ec*Ec];
__device__ __half g_Wo[(size_t)Ec*Ec];

// ---- helpers --------------------------------------------------------------
__device__ __forceinline__ uint32_t packh2(float a, float b) {
    __half2 h = __floats2half2_rn(a, b);
    return *(uint32_t*)&h;
}

// fp16 m16n8k16
__device__ __forceinline__ void mma16(float* d, const uint32_t* a, const uint32_t* b) {
    asm volatile(
        "mma.sync.aligned.m16n8k16.row.col.f32.f16.f16.f32 "
        "{%0,%1,%2,%3}, {%4,%5,%6,%7}, {%8,%9}, {%0,%1,%2,%3};"
        : "+f"(d[0]), "+f"(d[1]), "+f"(d[2]), "+f"(d[3])
        : "r"(a[0]), "r"(a[1]), "r"(a[2]), "r"(a[3]), "r"(b[0]), "r"(b[1]));
}

__device__ __forceinline__ void mbar_init(uint32_t a, uint32_t cnt) {
    asm volatile("mbarrier.init.shared.b64 [%0], %1;" :: "r"(a), "r"(cnt) : "memory");
}
__device__ __forceinline__ void mbar_expect(uint32_t a, uint32_t bytes) {
    asm volatile("mbarrier.arrive.expect_tx.shared.b64 _, [%0], %1;"
                 :: "r"(a), "r"(bytes) : "memory");
}
__device__ __forceinline__ void mbar_wait(uint32_t a, uint32_t par) {
    asm volatile(
        "{\n\t.reg .pred P;\n\t"
        "LW%=:\n\t"
        "mbarrier.try_wait.parity.acquire.cta.shared::cta.b64 P, [%0], %1, 0x989680;\n\t"
        "@P bra LD%=;\n\t"
        "bra LW%=;\n\t"
        "LD%=:\n\t}"
        :: "r"(a), "r"(par) : "memory");
}
__device__ __forceinline__ void tma2d(uint32_t dst, const CUtensorMap* m,
                                      int x, int y, uint32_t mb) {
    asm volatile(
        "cp.async.bulk.tensor.2d.shared::cta.global.tile.mbarrier::complete_tx::bytes "
        "[%0], [%1, {%2, %3}], [%4];"
        :: "r"(dst), "l"(m), "r"(x), "r"(y), "r"(mb) : "memory");
}
__device__ __forceinline__ void tma3d(uint32_t dst, const CUtensorMap* m,
                                      int x, int y, int z, uint32_t mb) {
    asm volatile(
        "cp.async.bulk.tensor.3d.shared::cta.global.tile.mbarrier::complete_tx::bytes "
        "[%0], [%1, {%2, %3, %4}], [%5];"
        :: "r"(dst), "l"(m), "r"(x), "r"(y), "r"(z), "r"(mb) : "memory");
}

// ---- pre-convert kernels --------------------------------------------------
__global__ __launch_bounds__(256) void cvt_f16(
    const float* __restrict__ in, __half* __restrict__ out, int n4)
{
    const int i = blockIdx.x * 256 + threadIdx.x;
    if (i < n4) {
        float4 v = ((const float4*)in)[i];
        __half2* o2 = (__half2*)out + 2 * i;
        o2[0] = __floats2half2_rn(v.x, v.y);
        o2[1] = __floats2half2_rn(v.z, v.w);
    }
}

// transpose + convert to fp16: out[n][k] = f16(in[k][n]); 32x32 smem tiles
__global__ __launch_bounds__(256) void cvt_tr16(
    const float* __restrict__ in, __half* __restrict__ out)
{
    __shared__ float t[32][33];
    const int n0 = blockIdx.x * 32, k0 = blockIdx.y * 32;
    const int tx = threadIdx.x & 31, ty = threadIdx.x >> 5;   // 32 x 8
    #pragma unroll
    for (int j = 0; j < 4; j++)
        t[ty * 4 + j][tx] = in[(size_t)(k0 + ty * 4 + j) * Ec + n0 + tx];
    __syncthreads();
    #pragma unroll
    for (int j = 0; j < 4; j++)
        out[(size_t)(n0 + ty * 4 + j) * Ec + k0 + tx] =
            __float2half_rn(t[tx][ty * 4 + j]);
}

// ---------------- GEMM fp16 (TMA, 3-stage, fused z) ------------------------
// A smem [128 m][64 k] halves SW128 (32 words/row), W smem [128 n][64 k].
// 128x128 tile, BK=64, 256 threads, warp tile 64x32, m16n8k16.
// MODE 1: QKV projection -- z<2 write fp16 [bh][s][d]; z==2 write fp16
//         TRANSPOSED [bh][d][s].  MODE 0: final, f32 row-major.
#define GBM 128
#define GBN 128
#define GBK 64
#define GSTG 32768
#define GMB  98304
#define GSMEM 98328

template<int MODE>
__global__ __launch_bounds__(256, 2) void gemm_tc(
    const __grid_constant__ CUtensorMap mA,
    const __grid_constant__ CUtensorMap mW0,
    const __grid_constant__ CUtensorMap mW1,
    const __grid_constant__ CUtensorMap mW2,
    const float* __restrict__ b0, const float* __restrict__ b1,
    const float* __restrict__ b2,
    void* __restrict__ C0, void* __restrict__ C1, void* __restrict__ C2)
{
    extern __shared__ char smem[];
    uint32_t smb;
    asm("{ .reg .u64 t; cvta.to.shared.u64 t, %1; cvt.u32.u64 %0, t; }"
        : "=r"(smb) : "l"(smem));

    const int z = blockIdx.z;
    const CUtensorMap* mW = (z == 0) ? &mW0 : (z == 1) ? &mW1 : &mW2;
    const float* bias = (z == 0) ? b0 : (z == 1) ? b1 : b2;
    void* C = (z == 0) ? C0 : (z == 1) ? C1 : C2;

    const int tid  = threadIdx.x;
    const int lane = tid & 31, warp = tid >> 5;
    const int g = lane >> 2, tg = lane & 3;
    const int wm = warp >> 2, wn = warp & 3;
    const int bm = blockIdx.y * GBM, bn = blockIdx.x * GBN;
    const int xg = 4 * g;

    if (tid == 0) {
        mbar_init(smb + GMB, 1); mbar_init(smb + GMB + 8, 1);
        mbar_init(smb + GMB + 16, 1);
    }
    __syncthreads();
    if (tid == 0) {
        #pragma unroll
        for (int s = 0; s < 2; s++) {
            const uint32_t mb = smb + GMB + 8 * s;
            mbar_expect(mb, GSTG);
            tma2d(smb + GSTG * s,         &mA, s * GBK, bm, mb);
            tma2d(smb + GSTG * s + 16384, mW,  s * GBK, bn, mb);
        }
    }

    float acc[4][4][4];
    #pragma unroll
    for (int mt = 0; mt < 4; mt++)
        #pragma unroll
        for (int nt = 0; nt < 4; nt++)
            #pragma unroll
            for (int i = 0; i < 4; i++) acc[mt][nt][i] = 0.f;

    const int NIT = Ec / GBK;   // 16
    for (int it = 0; it < NIT; it++) {
        const int sl = it % 3;
        if (it) __syncthreads();
        if (tid == 0 && it + 2 < NIT) {
            const int s2 = (it + 2) % 3;
            const uint32_t mb = smb + GMB + 8 * s2;
            mbar_expect(mb, GSTG);
            tma2d(smb + GSTG * s2,         &mA, (it + 2) * GBK, bm, mb);
            tma2d(smb + GSTG * s2 + 16384, mW,  (it + 2) * GBK, bn, mb);
        }
        mbar_wait(smb + GMB + 8 * sl, (it / 3) & 1);

        const uint32_t* Au = (const uint32_t*)(smem + GSTG * sl);
        const uint32_t* Wu = (const uint32_t*)(smem + GSTG * sl + 16384);

        #pragma unroll
        for (int ks = 0; ks < 4; ks++) {
            const int c0 = (8 * ks + tg) ^ xg;
            const int c4 = (8 * ks + tg + 4) ^ xg;
            uint32_t af[4][4], bf[4][2];
            #pragma unroll
            for (int mt = 0; mt < 4; mt++) {
                const int r = wm * 64 + mt * 16 + g;
                af[mt][0] = Au[r * 32 + c0];
                af[mt][1] = Au[(r + 8) * 32 + c0];
                af[mt][2] = Au[r * 32 + c4];
                af[mt][3] = Au[(r + 8) * 32 + c4];
            }
            #pragma unroll
            for (int nt = 0; nt < 4; nt++) {
                const int cb = wn * 32 + nt * 8 + g;
                bf[nt][0] = Wu[cb * 32 + c0];
                bf[nt][1] = Wu[cb * 32 + c4];
            }
            #pragma unroll
            for (int mt = 0; mt < 4; mt++)
                #pragma unroll
                for (int nt = 0; nt < 4; nt++)
                    mma16(acc[mt][nt], af[mt], bf[nt]);
        }
    }

    #pragma unroll
    for (int mt = 0; mt < 4; mt++) {
        #pragma unroll
        for (int half = 0; half < 2; half++) {
            const int m = bm + wm * 64 + mt * 16 + g + half * 8;
            #pragma unroll
            for (int nt = 0; nt < 4; nt++) {
                const int n = bn + wn * 32 + nt * 8 + 2 * tg;
                float2 bb = *(const float2*)&bias[n];
                float v0 = acc[mt][nt][half * 2 + 0] + bb.x;
                float v1 = acc[mt][nt][half * 2 + 1] + bb.y;
                if (MODE == 1) {
                    const int b = m >> 11, s = m & 2047;
                    const int h = n >> 6, d = n & 63;
                    __half* Ch = (__half*)C;
                    if (z < 2) {
                        *(__half2*)&Ch[(((size_t)(b * Hc + h)) * Sc + s) * Dc + d] =
                            __floats2half2_rn(v0, v1);
                    } else {   // V: transposed [bh][d][s]
                        const size_t base =
                            ((size_t)(b * Hc + h) * Dc + d) * Sc + s;
                        Ch[base]      = __float2half_rn(v0);
                        Ch[base + Sc] = __float2half_rn(v1);
                    }
                } else {
                    *(float2*)&((float*)C)[(size_t)m * Ec + n] =
                        make_float2(v0, v1);
                }
            }
        }
    }
}

// ---------------- Flash attention (fp16 mma, P in regs, all-TMA) -----------
// Q smem [128 q][64 d] halves (16 KB), K stage [64 kv][64 d] (8 KB),
// V stage [64 d][64 kv] (8 KB, from transposed g_Vt). All SW128, 32-word rows.
// fp16 k16 A-frag packs k-pairs == S-accumulator column pairs: P stays in
// registers with NO permutation.
#define AQ 128
#define AK0 16384
#define AMB 49152
#define ASMEM 49176

__global__ __launch_bounds__(256, 2) void attn_tc(
    __half* __restrict__ Ag_,
    const __grid_constant__ CUtensorMap mQ,
    const __grid_constant__ CUtensorMap mK,
    const __grid_constant__ CUtensorMap mV)
{
    extern __shared__ char smem[];
    uint32_t smb;
    asm("{ .reg .u64 t; cvta.to.shared.u64 t, %1; cvt.u32.u64 %0, t; }"
        : "=r"(smb) : "l"(smem));

    const int tid  = threadIdx.x;
    const int lane = tid & 31, warp = tid >> 5;
    const int g = lane >> 2, tg = lane & 3;
    const int q0 = warp * 16;
    const int xg = 4 * g;

    const int qt = blockIdx.x, h = blockIdx.y, b = blockIdx.z;
    const int bh = b * Hc + h;

    if (tid == 0) {
        mbar_init(smb + AMB, 1); mbar_init(smb + AMB + 8, 1);
        mbar_init(smb + AMB + 16, 1);
    }
    __syncthreads();
    if (tid == 0) {
        mbar_expect(smb + AMB + 16, 16384);
        tma3d(smb, &mQ, 0, qt * AQ, bh, smb + AMB + 16);     // Q once
        mbar_expect(smb + AMB, 16384);
        tma3d(smb + AK0,        &mK, 0, 0, bh, smb + AMB);   // K tile 0
        tma3d(smb + AK0 + 8192, &mV, 0, 0, bh, smb + AMB);   // V tile 0
    }

    float o[8][4];
    float mrow[2], lrow[2];
    #pragma unroll
    for (int nt = 0; nt < 8; nt++)
        #pragma unroll
        for (int i = 0; i < 4; i++) o[nt][i] = 0.f;
    mrow[0] = mrow[1] = -INFINITY;
    lrow[0] = lrow[1] = 0.f;

    mbar_wait(smb + AMB + 16, 0);   // Q ready
    const uint32_t* Qu = (const uint32_t*)smem;

    const int NT = Sc / 64;   // 32
    for (int kt = 0; kt < NT; kt++) {
        const int p = kt & 1;
        if (kt) __syncthreads();
        if (tid == 0 && kt + 1 < NT) {
            const uint32_t mb = smb + AMB + 8 * (1 - p);
            const int kv0 = (kt + 1) * 64;
            mbar_expect(mb, 16384);
            tma3d(smb + AK0 + 16384 * (1 - p),        &mK, 0, kv0, bh, mb);
            tma3d(smb + AK0 + 16384 * (1 - p) + 8192, &mV, kv0, 0, bh, mb);
        }
        mbar_wait(smb + AMB + 8 * p, (kt >> 1) & 1);

        const uint32_t* Ku = (const uint32_t*)(smem + AK0 + 16384 * p);
        const uint32_t* Vu = (const uint32_t*)(smem + AK0 + 16384 * p + 8192);

        // S = Q K^T : 4 k16-steps over d, 8 n8 tiles over kv
        float s[8][4];
        #pragma unroll
        for (int nt = 0; nt < 8; nt++)
            #pragma unroll
            for (int i = 0; i < 4; i++) s[nt][i] = 0.f;

        #pragma unroll
        for (int ks = 0; ks < 4; ks++) {
            const int c0 = (8 * ks + tg) ^ xg;
            const int c4 = (8 * ks + tg + 4) ^ xg;
            uint32_t af[4];
            af[0] = Qu[(q0 + g) * 32 + c0];
            af[1] = Qu[(q0 + 8 + g) * 32 + c0];
            af[2] = Qu[(q0 + g) * 32 + c4];
            af[3] = Qu[(q0 + 8 + g) * 32 + c4];
            #pragma unroll
            for (int nt = 0; nt < 8; nt++) {
                const int row = (8 * nt + g) * 32;
                uint32_t bf[2];
                bf[0] = Ku[row + c0];
                bf[1] = Ku[row + c4];
                mma16(s[nt], af, bf);
            }
        }
        // s[nt][0,1] = S(q0+g,   kv=8nt+2tg, +1); s[nt][2,3] = row q0+8+g

        // Online softmax (scale 0.125; rows spread over 4-lane quad)
        #pragma unroll
        for (int half = 0; half < 2; half++) {
            float tmax = -INFINITY;
            #pragma unroll
            for (int nt = 0; nt < 8; nt++) {
                s[nt][half * 2 + 0] *= 0.125f;
                s[nt][half * 2 + 1] *= 0.125f;
                tmax = fmaxf(tmax, s[nt][half * 2 + 0]);
                tmax = fmaxf(tmax, s[nt][half * 2 + 1]);
            }
            tmax = fmaxf(tmax, __shfl_xor_sync(0xffffffffu, tmax, 1));
            tmax = fmaxf(tmax, __shfl_xor_sync(0xffffffffu, tmax, 2));
            const float mn   = fmaxf(mrow[half], tmax);
            const float corr = __expf(mrow[half] - mn);
            float rs = 0.f;
            #pragma unroll
            for (int nt = 0; nt < 8; nt++) {
                float p0 = __expf(s[nt][half * 2 + 0] - mn);
                float p1 = __expf(s[nt][half * 2 + 1] - mn);
                s[nt][half * 2 + 0] = p0;
                s[nt][half * 2 + 1] = p1;
                rs += p0 + p1;
                o[nt][half * 2 + 0] *= corr;
                o[nt][half * 2 + 1] *= corr;
            }
            rs += __shfl_xor_sync(0xffffffffu, rs, 1);
            rs += __shfl_xor_sync(0xffffffffu, rs, 2);
            lrow[half] = lrow[half] * corr + rs;
            mrow[half] = mn;
        }

        // O += P @ V : P packed straight from S accumulator (no permutation)
        #pragma unroll
        for (int ks = 0; ks < 4; ks++) {
            uint32_t af[4];
            af[0] = packh2(s[2 * ks][0],     s[2 * ks][1]);
            af[1] = packh2(s[2 * ks][2],     s[2 * ks][3]);
            af[2] = packh2(s[2 * ks + 1][0], s[2 * ks + 1][1]);
            af[3] = packh2(s[2 * ks + 1][2], s[2 * ks + 1][3]);
            const int c0 = (8 * ks + tg) ^ xg;
            const int c4 = (8 * ks + tg + 4) ^ xg;
            #pragma unroll
            for (int nt = 0; nt < 8; nt++) {
                const int row = (8 * nt + g) * 32;   // V rows are d
                uint32_t bf[2];
                bf[0] = Vu[row + c0];
                bf[1] = Vu[row + c4];
                mma16(o[nt], af, bf);
            }
        }
    }

    // Epilogue: normalize, write concat [B,S,E] as fp16 (for fp16 Wo GEMM)
    #pragma unroll
    for (int half = 0; half < 2; half++) {
        const float inv = 1.f / lrow[half];
        const int q = qt * AQ + q0 + g + half * 8;
        #pragma unroll
        for (int nt = 0; nt < 8; nt++) {
            const int d = nt * 8 + 2 * tg;
            __half2* dst = (__half2*)&Ag_[((size_t)b * Sc + q) * Ec + h * Dc + d];
            *dst = __floats2half2_rn(o[nt][half * 2 + 0] * inv,
                                     o[nt][half * 2 + 1] * inv);
        }
    }
}

// ---------------------------------------------------------------------------
typedef CUresult (*PFN_tmencode)(
    CUtensorMap*, CUtensorMapDataType, cuuint32_t, void*,
    const cuuint64_t*, const cuuint64_t*, const cuuint32_t*, const cuuint32_t*,
    CUtensorMapInterleave, CUtensorMapSwizzle, CUtensorMapL2promotion,
    CUtensorMapFloatOOBfill);

static void enc2d(PFN_tmencode fn, CUtensorMap* m, void* base,
                  uint64_t d0, uint64_t d1, uint64_t stride1B,
                  uint32_t b0, uint32_t b1)
{
    cuuint64_t dims[2] = {d0, d1};
    cuuint64_t str[1]  = {stride1B};
    cuuint32_t box[2]  = {b0, b1};
    cuuint32_t es[2]   = {1, 1};
    fn(m, CU_TENSOR_MAP_DATA_TYPE_FLOAT16, 2, base, dims, str, box, es,
       CU_TENSOR_MAP_INTERLEAVE_NONE, CU_TENSOR_MAP_SWIZZLE_128B,
       CU_TENSOR_MAP_L2_PROMOTION_L2_128B, CU_TENSOR_MAP_FLOAT_OOB_FILL_NONE);
}

static void enc3d(PFN_tmencode fn, CUtensorMap* m, void* base,
                  uint64_t d0, uint64_t d1, uint32_t b0, uint32_t b1)
{
    cuuint64_t dims[3] = {d0, d1, BH};
    cuuint64_t str[2]  = {d0 * 2ull, d0 * d1 * 2ull};
    cuuint32_t box[3]  = {b0, b1, 1};
    cuuint32_t es[3]   = {1, 1, 1};
    fn(m, CU_TENSOR_MAP_DATA_TYPE_FLOAT16, 3, base, dims, str, box, es,
       CU_TENSOR_MAP_INTERLEAVE_NONE, CU_TENSOR_MAP_SWIZZLE_128B,
       CU_TENSOR_MAP_L2_PROMOTION_L2_128B, CU_TENSOR_MAP_FLOAT_OOB_FILL_NONE);
}

extern "C" void kernel_launch(void* const* d_in, const int* in_sizes, int n_in,
                              void* d_out, int out_size)
{
    const float* x  = (const float*)d_in[0];
    const float* Wq = (const float*)d_in[1];
    const float* bq = (const float*)d_in[2];
    const float* Wk = (const float*)d_in[3];
    const float* bk = (const float*)d_in[4];
    const float* Wv = (const float*)d_in[5];
    const float* bv = (const float*)d_in[6];
    const float* Wo = (const float*)d_in[7];
    const float* bo = (const float*)d_in[8];
    float* out = (float*)d_out;

    __half *pQ, *pK, *pV, *pAh, *pXh, *pWq, *pWk, *pWv, *pWo;
    cudaGetSymbolAddress((void**)&pQ, g_Qh);
    cudaGetSymbolAddress((void**)&pK, g_Kh);
    cudaGetSymbolAddress((void**)&pV, g_Vt);
    cudaGetSymbolAddress((void**)&pAh, g_Ah);
    cudaGetSymbolAddress((void**)&pXh, g_Xh);
    cudaGetSymbolAddress((void**)&pWq, g_Wq);
    cudaGetSymbolAddress((void**)&pWk, g_Wk);
    cudaGetSymbolAddress((void**)&pWv, g_Wv);
    cudaGetSymbolAddress((void**)&pWo, g_Wo);

    PFN_tmencode enc = nullptr;
    {
        void* fn = nullptr;
        cudaDriverEntryPointQueryResult qr;
        cudaGetDriverEntryPointByVersion("cuTensorMapEncodeTiled", &fn, 12000,
                                         cudaEnableDefault, &qr);
        enc = (PFN_tmencode)fn;
    }

    CUtensorMap mX, mWq, mWk, mWv, mWo, mAo, mQm, mKm, mVm;
    enc2d(enc, &mX,  pXh, Ec, Mtot, Ec * 2ull, GBK, GBM);
    enc2d(enc, &mWq, pWq, Ec, Ec,   Ec * 2ull, GBK, GBN);
    enc2d(enc, &mWk, pWk, Ec, Ec,   Ec * 2ull, GBK, GBN);
    enc2d(enc, &mWv, pWv, Ec, Ec,   Ec * 2ull, GBK, GBN);
    enc2d(enc, &mWo, pWo, Ec, Ec,   Ec * 2ull, GBK, GBN);
    enc2d(enc, &mAo, pAh, Ec, Mtot, Ec * 2ull, GBK, GBM);
    enc3d(enc, &mQm, pQ, Dc, Sc, 64, 128);   // [bh][s][d], box 64d x 128q
    enc3d(enc, &mKm, pK, Dc, Sc, 64, 64);    // [bh][s][d], box 64d x 64kv
    enc3d(enc, &mVm, pV, Sc, Dc, 64, 64);    // [bh][d][s], box 64s x 64d

    cudaFuncSetAttribute(gemm_tc<0>, cudaFuncAttributeMaxDynamicSharedMemorySize, GSMEM);
    cudaFuncSetAttribute(gemm_tc<1>, cudaFuncAttributeMaxDynamicSharedMemorySize, GSMEM);
    cudaFuncSetAttribute(attn_tc, cudaFuncAttributeMaxDynamicSharedMemorySize, ASMEM);

    const int xN4 = Mtot * Ec / 4;
    cvt_f16<<<(xN4 + 255) / 256, 256>>>(x, pXh, xN4);
    dim3 tgv(Ec / 32, Ec / 32);
    cvt_tr16<<<tgv, 256>>>(Wq, pWq);
    cvt_tr16<<<tgv, 256>>>(Wk, pWk);
    cvt_tr16<<<tgv, 256>>>(Wv, pWv);
    cvt_tr16<<<tgv, 256>>>(Wo, pWo);

    // fused Q/K/V projection (fp16): z selects weight/bias/out; V transposed
    gemm_tc<1><<<dim3(Ec / GBN, Mtot / GBM, 3), 256, GSMEM>>>(
        mX, mWq, mWk, mWv, bq, bk, bv, pQ, pK, pV);
    attn_tc<<<dim3(Sc / AQ, Hc, Bc), 256, ASMEM>>>(pAh, mQm, mKm, mVm);
    gemm_tc<0><<<dim3(Ec / GBN, Mtot / GBM, 1), 256, GSMEM>>>(
        mAo, mWo, mWo, mWo, bo, bo, bo, out, out, out);
}